// round 2
// baseline (speedup 1.0000x reference)
#include <cuda_runtime.h>
#include <math.h>

#define kN 8192      // total nodes (= rows/cols of adj)
#define kC 256       // channels / nodes per graph
#define kB 32        // graphs
#define kH 128       // hidden
#define kE 131072    // edges
#define kNN ((size_t)kN * (size_t)kN)

// ---------------- scratch (static device globals; no allocation) ----------------
__device__ __align__(16) float g_PA[kNN];          // 256 MB: blockdiag(P)@adj accumulator
__device__ __align__(16) float g_Pt[kB * kC * kC]; // 8 MB: transposed selected pert blocks
__device__ __align__(16) float g_XW[kN * kH];      // 4 MB: h @ W buffer
__device__ __align__(16) float g_Hb[kN * kH];      // 4 MB: SpMM output buffer

// ---------------- utility ----------------
__global__ void zeroBuf(float4* __restrict__ p) {
    p[(size_t)blockIdx.x * blockDim.x + threadIdx.x] = make_float4(0.f, 0.f, 0.f, 0.f);
}

__device__ __forceinline__ float hard_sig(float v) {
    // reference: 0 if sigmoid(v) <= 0.5 else 1, in f32
    float s = 1.f / (1.f + expf(-v));
    return (s > 0.5f) ? 1.f : 0.f;
}

// g_Pt[b][k][i] = pert_W[graph_id[b]][i][k]
__global__ void transposeP(const float* __restrict__ pW, const int* __restrict__ gid) {
    int b = blockIdx.x, k = blockIdx.y, i = threadIdx.x;
    g_Pt[((size_t)b * kC + k) * kC + i] =
        pW[(size_t)gid[b] * kC * kC + (size_t)i * kC + k];
}

// adj[r, c] += 1 per edge
__global__ void scatterAdj(const int* __restrict__ ei, float* __restrict__ adj) {
    int e = blockIdx.x * blockDim.x + threadIdx.x;
    if (e < kE) {
        int r = ei[e], c = ei[kE + e];
        atomicAdd(adj + (size_t)r * kN + c, 1.0f);
    }
}

// per edge (r,c): PA[(b*256 + i), c] += P_b[i, r%256]   (b = r/256)
__global__ void scatterPA(const int* __restrict__ ei) {
    int e = blockIdx.x;
    int r = __ldg(&ei[e]);
    int c = __ldg(&ei[kE + e]);
    int b = r >> 8, k = r & 255;
    float v = g_Pt[((size_t)b * kC + k) * kC + threadIdx.x];
    atomicAdd(&g_PA[((size_t)(b * kC + threadIdx.x)) * kN + c], v);
}

// pert_adj = hard_where(sigmoid(PA + blockdiag bias))
__global__ void thresholdPA(float* __restrict__ pert, const float* __restrict__ pb,
                            const int* __restrict__ gid) {
    size_t i4 = (size_t)blockIdx.x * blockDim.x + threadIdx.x;
    size_t e0 = i4 * 4;
    int i = (int)(e0 >> 13);     // row
    int j = (int)(e0 & 8191);    // col (multiple of 4)
    float4 v = *(const float4*)&g_PA[e0];
    int b = i >> 8;
    if ((j >> 8) == b) {
        float4 bias = *(const float4*)&pb[(size_t)gid[b] * kC * kC +
                                          (size_t)(i & 255) * kC + (j & 255)];
        v.x += bias.x; v.y += bias.y; v.z += bias.z; v.w += bias.w;
    }
    float4 o;
    o.x = hard_sig(v.x); o.y = hard_sig(v.y); o.z = hard_sig(v.z); o.w = hard_sig(v.w);
    *(float4*)&pert[e0] = o;
}

// M = hard_where(sigmoid(mask_W[graph_id] reshaped)), x_masked = M * x
__global__ void maskK(const float* __restrict__ x, const float* __restrict__ mW,
                      const int* __restrict__ gid,
                      float* __restrict__ Mo, float* __restrict__ xm) {
    size_t i4 = (size_t)blockIdx.x * blockDim.x + threadIdx.x;
    size_t e0 = i4 * 4;
    int n = (int)(e0 >> 8);
    int c = (int)(e0 & 255);
    int b = n >> 8;
    float4 w = *(const float4*)&mW[(size_t)gid[b] * kC * kC + (size_t)(n & 255) * kC + c];
    float4 xv = *(const float4*)&x[e0];
    float4 m, o;
    m.x = hard_sig(w.x); m.y = hard_sig(w.y); m.z = hard_sig(w.z); m.w = hard_sig(w.w);
    o.x = m.x * xv.x; o.y = m.y * xv.y; o.z = m.z * xv.z; o.w = m.w * xv.w;
    *(float4*)&Mo[e0] = m;
    *(float4*)&xm[e0] = o;
}

// sparse SpMM: g_Hb[r, :] += src[c, :] per edge
__global__ void spmmE(const int* __restrict__ ei, const float* __restrict__ src) {
    int e = blockIdx.x;
    int r = __ldg(&ei[e]);
    int c = __ldg(&ei[kE + e]);
    atomicAdd(&g_Hb[(size_t)r * kH + threadIdx.x], src[(size_t)c * kH + threadIdx.x]);
}

// ---------------- tiled fp32 GEMM: C[M=8192 x 128] = op(A)[8192 x K] @ B[K x 128] ----------------
// BM=64, BN=128, BK=32. 256 threads, each computes 8x4. Global->reg prefetch overlaps compute.
template <bool RELU_A>
__global__ __launch_bounds__(256) void gemm128(const float* __restrict__ A,
                                               const float* __restrict__ Bm,
                                               float* __restrict__ Cm, int K) {
    __shared__ float As[32][65];   // [kk][row], padded: conflict-free transpose store
    __shared__ float Bs[32][128];  // [kk][col]
    const int tid = threadIdx.x;
    const int row0 = blockIdx.x * 64;
    const int nk = K >> 5;
    const int ar = tid >> 3;           // 0..31
    const int ac = (tid & 7) << 2;     // 0,4,...,28
    const int ty = tid >> 5;           // 0..7 -> rows ty*8..+7
    const int tx = tid & 31;           // cols tx*4..+3
    const int br = tid >> 5;           // 0..7 (+8 per chunk)
    const int bc = (tid & 31) << 2;

    const float* Arow0 = A + (size_t)(row0 + ar) * K;
    const float* Arow1 = A + (size_t)(row0 + ar + 32) * K;

    float acc[8][4];
#pragma unroll
    for (int i = 0; i < 8; i++)
#pragma unroll
        for (int j = 0; j < 4; j++) acc[i][j] = 0.f;

    float4 pa0 = *(const float4*)(Arow0 + ac);
    float4 pa1 = *(const float4*)(Arow1 + ac);
    float4 pb0 = *(const float4*)&Bm[(size_t)(br) * kH + bc];
    float4 pb1 = *(const float4*)&Bm[(size_t)(br + 8) * kH + bc];
    float4 pb2 = *(const float4*)&Bm[(size_t)(br + 16) * kH + bc];
    float4 pb3 = *(const float4*)&Bm[(size_t)(br + 24) * kH + bc];

    for (int kt = 0; kt < nk; kt++) {
        __syncthreads();
        if (RELU_A) {
            pa0.x = fmaxf(pa0.x, 0.f); pa0.y = fmaxf(pa0.y, 0.f);
            pa0.z = fmaxf(pa0.z, 0.f); pa0.w = fmaxf(pa0.w, 0.f);
            pa1.x = fmaxf(pa1.x, 0.f); pa1.y = fmaxf(pa1.y, 0.f);
            pa1.z = fmaxf(pa1.z, 0.f); pa1.w = fmaxf(pa1.w, 0.f);
        }
        As[ac + 0][ar] = pa0.x; As[ac + 1][ar] = pa0.y;
        As[ac + 2][ar] = pa0.z; As[ac + 3][ar] = pa0.w;
        As[ac + 0][ar + 32] = pa1.x; As[ac + 1][ar + 32] = pa1.y;
        As[ac + 2][ar + 32] = pa1.z; As[ac + 3][ar + 32] = pa1.w;
        *(float4*)&Bs[br][bc] = pb0;
        *(float4*)&Bs[br + 8][bc] = pb1;
        *(float4*)&Bs[br + 16][bc] = pb2;
        *(float4*)&Bs[br + 24][bc] = pb3;
        __syncthreads();
        if (kt + 1 < nk) {
            int ko = (kt + 1) << 5;
            pa0 = *(const float4*)(Arow0 + ko + ac);
            pa1 = *(const float4*)(Arow1 + ko + ac);
            pb0 = *(const float4*)&Bm[(size_t)(ko + br) * kH + bc];
            pb1 = *(const float4*)&Bm[(size_t)(ko + br + 8) * kH + bc];
            pb2 = *(const float4*)&Bm[(size_t)(ko + br + 16) * kH + bc];
            pb3 = *(const float4*)&Bm[(size_t)(ko + br + 24) * kH + bc];
        }
#pragma unroll
        for (int kk = 0; kk < 32; kk++) {
            float a[8];
#pragma unroll
            for (int i = 0; i < 8; i++) a[i] = As[kk][ty * 8 + i];
            float4 b4 = *(const float4*)&Bs[kk][tx << 2];
#pragma unroll
            for (int i = 0; i < 8; i++) {
                acc[i][0] = fmaf(a[i], b4.x, acc[i][0]);
                acc[i][1] = fmaf(a[i], b4.y, acc[i][1]);
                acc[i][2] = fmaf(a[i], b4.z, acc[i][2]);
                acc[i][3] = fmaf(a[i], b4.w, acc[i][3]);
            }
        }
    }
#pragma unroll
    for (int i = 0; i < 8; i++) {
        float4 o = make_float4(acc[i][0], acc[i][1], acc[i][2], acc[i][3]);
        *(float4*)&Cm[(size_t)(row0 + ty * 8 + i) * kH + (tx << 2)] = o;
    }
}

// ---------------- pooling (mean+max over 256 nodes of relu(h3)) + MLP + sigmoid ----------------
__global__ void poolMlp(const float* __restrict__ mlpW, const float* __restrict__ mlpb,
                        float* __restrict__ outp) {
    int g = blockIdx.x, f = threadIdx.x; // 128 threads
    const float* base = g_Hb + (size_t)g * kC * kH;
    float s = 0.f, m = 0.f;
    for (int r = 0; r < kC; r++) {
        float v = base[(size_t)r * kH + f];
        v = v > 0.f ? v : 0.f;     // relu of final layer
        s += v;
        m = v > m ? v : m;
    }
    s *= (1.0f / kC);              // cnt is exactly 256 per graph
    float p0 = s * mlpW[f * 2 + 0] + m * mlpW[(kH + f) * 2 + 0];
    float p1 = s * mlpW[f * 2 + 1] + m * mlpW[(kH + f) * 2 + 1];
    __shared__ float r0[128], r1[128];
    r0[f] = p0; r1[f] = p1;
    __syncthreads();
    for (int st = 64; st > 0; st >>= 1) {
        if (f < st) { r0[f] += r0[f + st]; r1[f] += r1[f + st]; }
        __syncthreads();
    }
    if (f == 0) {
        float z0 = r0[0] + mlpb[0];
        float z1 = r1[0] + mlpb[1];
        outp[g * 2 + 0] = 1.f / (1.f + expf(-z0));
        outp[g * 2 + 1] = 1.f / (1.f + expf(-z1));
    }
}

// ---------------- driver ----------------
extern "C" void kernel_launch(void* const* d_in, const int* in_sizes, int n_in,
                              void* d_out, int out_size) {
    const float* x    = (const float*)d_in[0];
    const int*   ei   = (const int*)d_in[1];
    const int*   gid  = (const int*)d_in[2];
    /* d_in[3] = batch (structure known: arange//256) */
    const float* pW   = (const float*)d_in[4];
    const float* pb   = (const float*)d_in[5];
    const float* mW   = (const float*)d_in[6];
    const float* w0   = (const float*)d_in[7];
    const float* w1   = (const float*)d_in[8];
    const float* w2   = (const float*)d_in[9];
    const float* mlpW = (const float*)d_in[10];
    const float* mlpb = (const float*)d_in[11];

    float* out  = (float*)d_out;
    float* adj  = out;                           // [N*N]
    float* pert = out + kNN;                     // [N*N]
    float* Mo   = out + 2 * kNN;                 // [N*C]
    float* pred = Mo + (size_t)kN * kC;          // [B*2]
    float* aug  = pred + kB * 2;                 // [B*2]
    float* xm   = aug + kB * 2;                  // [N*C]

    float *PA, *XW, *Hb;
    cudaGetSymbolAddress((void**)&PA, g_PA);
    cudaGetSymbolAddress((void**)&XW, g_XW);
    cudaGetSymbolAddress((void**)&Hb, g_Hb);

    const int Z64M = (int)(kNN / 4 / 256);       // 65536 blocks of 256 float4
    const int ZH   = (int)((size_t)kN * kH / 4 / 256); // 1024

    // adjacency + PA accumulator
    zeroBuf<<<Z64M, 256>>>((float4*)adj);
    zeroBuf<<<Z64M, 256>>>((float4*)PA);
    transposeP<<<dim3(kB, kC), 256>>>(pW, gid);
    scatterAdj<<<kE / 256, 256>>>(ei, adj);
    scatterPA<<<kE, 256>>>(ei);
    thresholdPA<<<Z64M, 256>>>(pert, pb, gid);
    maskK<<<(int)((size_t)kN * kC / 4 / 256), 256>>>(x, mW, gid, Mo, xm);

    // ---- predictor on (x, adj) : sparse SpMM via edge scatter ----
    gemm128<false><<<kN / 64, 256>>>(x, w0, XW, kC);
    zeroBuf<<<ZH, 256>>>((float4*)Hb);
    spmmE<<<kE, 128>>>(ei, XW);
    gemm128<true><<<kN / 64, 256>>>(Hb, w1, XW, kH);
    zeroBuf<<<ZH, 256>>>((float4*)Hb);
    spmmE<<<kE, 128>>>(ei, XW);
    gemm128<true><<<kN / 64, 256>>>(Hb, w2, XW, kH);
    zeroBuf<<<ZH, 256>>>((float4*)Hb);
    spmmE<<<kE, 128>>>(ei, XW);
    poolMlp<<<kB, 128>>>(mlpW, mlpb, pred);

    // ---- predictor on (x_masked, pert_adj) : dense SpMM ----
    gemm128<false><<<kN / 64, 256>>>(xm, w0, XW, kC);
    gemm128<false><<<kN / 64, 256>>>(pert, XW, Hb, kN);
    gemm128<true><<<kN / 64, 256>>>(Hb, w1, XW, kH);
    gemm128<false><<<kN / 64, 256>>>(pert, XW, Hb, kN);
    gemm128<true><<<kN / 64, 256>>>(Hb, w2, XW, kH);
    gemm128<false><<<kN / 64, 256>>>(pert, XW, Hb, kN);
    poolMlp<<<kB, 128>>>(mlpW, mlpb, aug);
}

// round 6
// speedup vs baseline: 1.3220x; 1.3220x over previous
#include <cuda_runtime.h>
#include <cuda_bf16.h>
#include <math.h>
#include <stdint.h>

#define kN 8192      // total nodes
#define kC 256       // channels / nodes per graph
#define kB 32        // graphs
#define kH 128       // hidden
#define kE 131072    // edges
#define kNN ((size_t)kN * (size_t)kN)

// ---------------- scratch (static device globals; no allocation) ----------------
__device__ __align__(16) float g_PA[kNN];                    // 256 MB accumulator
__device__ __align__(16) float g_Pt[kB * kC * kC];           // 8 MB transposed P blocks
__device__ __align__(16) float g_XW[kN * kH];                // 4 MB  h @ W
__device__ __align__(16) float g_Hb[kN * kH];                // 4 MB  A @ XW
__device__ __align__(16) __nv_bfloat16 g_adjBF[kNN];         // 128 MB adj bf16 (exact: counts)
__device__ __align__(16) __nv_bfloat16 g_pertBF[kNN];        // 128 MB pert bf16 (exact: 0/1)
__device__ __align__(16) __nv_bfloat16 g_XWt[kH * kN];       // 2 MB  XW^T bf16 (K-major)

__device__ __forceinline__ uint32_t smem_u32(const void* p) {
    uint32_t a;
    asm("{ .reg .u64 t; cvta.to.shared.u64 t, %1; cvt.u32.u64 %0, t; }" : "=r"(a) : "l"(p));
    return a;
}

// ---------------- utility kernels ----------------
__global__ void zeroBuf(float4* __restrict__ p) {
    p[(size_t)blockIdx.x * blockDim.x + threadIdx.x] = make_float4(0.f, 0.f, 0.f, 0.f);
}
__device__ __forceinline__ float hard_sig(float v) {
    float s = 1.f / (1.f + expf(-v));
    return (s > 0.5f) ? 1.f : 0.f;
}
__global__ void transposeP(const float* __restrict__ pW, const int* __restrict__ gid) {
    int b = blockIdx.x, k = blockIdx.y, i = threadIdx.x;
    g_Pt[((size_t)b * kC + k) * kC + i] = pW[(size_t)gid[b] * kC * kC + (size_t)i * kC + k];
}
__global__ void scatterAdj(const int* __restrict__ ei, float* __restrict__ adj) {
    int e = blockIdx.x * blockDim.x + threadIdx.x;
    if (e < kE) {
        int r = ei[e], c = ei[kE + e];
        atomicAdd(adj + (size_t)r * kN + c, 1.0f);
    }
}
__global__ void scatterPA(const int* __restrict__ ei) {
    int e = blockIdx.x;
    int r = __ldg(&ei[e]);
    int c = __ldg(&ei[kE + e]);
    int b = r >> 8, k = r & 255;
    float v = g_Pt[((size_t)b * kC + k) * kC + threadIdx.x];
    atomicAdd(&g_PA[((size_t)(b * kC + threadIdx.x)) * kN + c], v);
}
// pert = hard_where(sigmoid(PA + blockdiag bias)); also emit bf16 copy for MMA
__global__ void thresholdPA(float* __restrict__ pert, const float* __restrict__ pb,
                            const int* __restrict__ gid) {
    size_t i4 = (size_t)blockIdx.x * blockDim.x + threadIdx.x;
    size_t e0 = i4 * 4;
    int i = (int)(e0 >> 13);
    int j = (int)(e0 & 8191);
    float4 v = *(const float4*)&g_PA[e0];
    int b = i >> 8;
    if ((j >> 8) == b) {
        float4 bias = *(const float4*)&pb[(size_t)gid[b] * kC * kC +
                                          (size_t)(i & 255) * kC + (j & 255)];
        v.x += bias.x; v.y += bias.y; v.z += bias.z; v.w += bias.w;
    }
    float4 o;
    o.x = hard_sig(v.x); o.y = hard_sig(v.y); o.z = hard_sig(v.z); o.w = hard_sig(v.w);
    *(float4*)&pert[e0] = o;
    __nv_bfloat162* pb2 = (__nv_bfloat162*)g_pertBF;
    pb2[i4 * 2]     = __floats2bfloat162_rn(o.x, o.y);
    pb2[i4 * 2 + 1] = __floats2bfloat162_rn(o.z, o.w);
}
__global__ void cvtBF(const float4* __restrict__ src, __nv_bfloat162* __restrict__ dst) {
    size_t i = (size_t)blockIdx.x * blockDim.x + threadIdx.x;
    float4 v = src[i];
    dst[2 * i]     = __floats2bfloat162_rn(v.x, v.y);
    dst[2 * i + 1] = __floats2bfloat162_rn(v.z, v.w);
}
__global__ void maskK(const float* __restrict__ x, const float* __restrict__ mW,
                      const int* __restrict__ gid,
                      float* __restrict__ Mo, float* __restrict__ xm) {
    size_t i4 = (size_t)blockIdx.x * blockDim.x + threadIdx.x;
    size_t e0 = i4 * 4;
    int n = (int)(e0 >> 8);
    int c = (int)(e0 & 255);
    int b = n >> 8;
    float4 w = *(const float4*)&mW[(size_t)gid[b] * kC * kC + (size_t)(n & 255) * kC + c];
    float4 xv = *(const float4*)&x[e0];
    float4 m, o;
    m.x = hard_sig(w.x); m.y = hard_sig(w.y); m.z = hard_sig(w.z); m.w = hard_sig(w.w);
    o.x = m.x * xv.x; o.y = m.y * xv.y; o.z = m.z * xv.z; o.w = m.w * xv.w;
    *(float4*)&Mo[e0] = m;
    *(float4*)&xm[e0] = o;
}
// XWt[n][k] = bf16(XW[k][n]) ; XW is [kN, kH]
__global__ void transB(const float* __restrict__ XW, __nv_bfloat16* __restrict__ Bt) {
    __shared__ float t[32][33];
    int k0 = blockIdx.x * 32, n0 = blockIdx.y * 32;
    int tx = threadIdx.x, ty = threadIdx.y;  // 32 x 8
#pragma unroll
    for (int j = 0; j < 32; j += 8)
        t[ty + j][tx] = XW[(size_t)(k0 + ty + j) * kH + n0 + tx];
    __syncthreads();
#pragma unroll
    for (int j = 0; j < 32; j += 8)
        Bt[(size_t)(n0 + ty + j) * kN + k0 + tx] = __float2bfloat16(t[tx][ty + j]);
}

// ---------------- HMMA bf16 GEMM: C[8192 x 128] = A[8192 x 8192] @ Bt^T ----------------
// A bf16 row-major; Bt bf16 [128 x 8192] (K-major per output column).
// BM=64, BN=128, BK=32. 256 threads = 8 warps (2 x 4), warp tile 32x32.
// smem rows padded to 80B: ldmatrix row banks r*20 mod 32 all-distinct -> conflict-free.
#define NKCH (kN / 32)      // 256 k-chunks
#define ABUF (64 * 80)      // 5120 B per A buffer
#define BBUF (128 * 80)     // 10240 B per B buffer

__global__ __launch_bounds__(256) void hmmaGemm(const __nv_bfloat16* __restrict__ Abf,
                                                const __nv_bfloat16* __restrict__ Bt,
                                                float* __restrict__ C) {
    __shared__ __align__(16) unsigned char smA[2 * ABUF];
    __shared__ __align__(16) unsigned char smB[2 * BBUF];
    const int tid = threadIdx.x;
    const int lane = tid & 31, wid = tid >> 5;
    const int wm = wid >> 2, wn = wid & 3;
    const int row0 = blockIdx.x * 64;

    const uint32_t saBase = smem_u32(smA);
    const uint32_t sbBase = smem_u32(smB);

    // cp.async mapping: thread -> (row = tid/4, 16B segment = tid%4)
    const int ar = tid >> 2, aseg = tid & 3;
    const __nv_bfloat16* aSrc  = Abf + (size_t)(row0 + ar) * kN + aseg * 8;
    const __nv_bfloat16* bSrc0 = Bt + (size_t)ar * kN + aseg * 8;
    const __nv_bfloat16* bSrc1 = Bt + (size_t)(ar + 64) * kN + aseg * 8;
    const uint32_t aDst  = saBase + ar * 80 + aseg * 16;
    const uint32_t bDst0 = sbBase + ar * 80 + aseg * 16;
    const uint32_t bDst1 = sbBase + (ar + 64) * 80 + aseg * 16;

#define LOADCH(kt, bi) do {                                                           \
        int kk_ = (kt) * 32;                                                          \
        asm volatile("cp.async.cg.shared.global [%0], [%1], 16;"                      \
                     :: "r"(aDst + (bi) * ABUF), "l"(aSrc + kk_) : "memory");         \
        asm volatile("cp.async.cg.shared.global [%0], [%1], 16;"                      \
                     :: "r"(bDst0 + (bi) * BBUF), "l"(bSrc0 + kk_) : "memory");       \
        asm volatile("cp.async.cg.shared.global [%0], [%1], 16;"                      \
                     :: "r"(bDst1 + (bi) * BBUF), "l"(bSrc1 + kk_) : "memory");       \
        asm volatile("cp.async.commit_group;" ::: "memory");                          \
    } while (0)

    float acc[2][4][4];
#pragma unroll
    for (int mt = 0; mt < 2; mt++)
#pragma unroll
        for (int nt = 0; nt < 4; nt++)
#pragma unroll
            for (int q = 0; q < 4; q++) acc[mt][nt][q] = 0.f;

    // ldmatrix per-lane address components (byte offsets within a buffer)
    const int l15 = lane & 15;
    const uint32_t aLm0 = (uint32_t)((wm * 32 + l15) * 80 + ((lane >> 4) & 1) * 16);
    const uint32_t bLmRow = (uint32_t)((wn * 32 + (l15 & 7)) * 80 + ((l15 >> 3) & 1) * 16);

    LOADCH(0, 0);

    for (int kt = 0; kt < NKCH; kt++) {
        const int cur = kt & 1;
        if (kt + 1 < NKCH) {
            LOADCH(kt + 1, cur ^ 1);
            asm volatile("cp.async.wait_group 1;" ::: "memory");
        } else {
            asm volatile("cp.async.wait_group 0;" ::: "memory");
        }
        __syncthreads();

        const uint32_t saB = saBase + cur * ABUF;
        const uint32_t sbB = sbBase + cur * BBUF;
#pragma unroll
        for (int ks = 0; ks < 2; ks++) {
            uint32_t af[2][4];
#pragma unroll
            for (int mt = 0; mt < 2; mt++) {
                uint32_t ad = saB + aLm0 + (uint32_t)(mt * 16 * 80 + ks * 32);
                asm volatile("ldmatrix.sync.aligned.m8n8.x4.shared.b16 {%0,%1,%2,%3}, [%4];"
                             : "=r"(af[mt][0]), "=r"(af[mt][1]), "=r"(af[mt][2]), "=r"(af[mt][3])
                             : "r"(ad));
            }
#pragma unroll
            for (int nt = 0; nt < 4; nt++) {
                uint32_t b0, b1;
                uint32_t bd = sbB + bLmRow + (uint32_t)(nt * 8 * 80 + ks * 32);
                asm volatile("ldmatrix.sync.aligned.m8n8.x2.shared.b16 {%0,%1}, [%2];"
                             : "=r"(b0), "=r"(b1) : "r"(bd));
#pragma unroll
                for (int mt = 0; mt < 2; mt++) {
                    asm volatile(
                        "mma.sync.aligned.m16n8k16.row.col.f32.bf16.bf16.f32 "
                        "{%0,%1,%2,%3}, {%4,%5,%6,%7}, {%8,%9}, {%0,%1,%2,%3};"
                        : "+f"(acc[mt][nt][0]), "+f"(acc[mt][nt][1]),
                          "+f"(acc[mt][nt][2]), "+f"(acc[mt][nt][3])
                        : "r"(af[mt][0]), "r"(af[mt][1]), "r"(af[mt][2]), "r"(af[mt][3]),
                          "r"(b0), "r"(b1));
                }
            }
        }
        __syncthreads();
    }

    // epilogue: c-frag thread mapping: rows lane/4 (+8), cols (lane%4)*2 (+1)
    const int crow = row0 + wm * 32 + (lane >> 2);
    const int ccol = wn * 32 + (lane & 3) * 2;
#pragma unroll
    for (int mt = 0; mt < 2; mt++) {
#pragma unroll
        for (int nt = 0; nt < 4; nt++) {
            float2 v0 = make_float2(acc[mt][nt][0], acc[mt][nt][1]);
            float2 v1 = make_float2(acc[mt][nt][2], acc[mt][nt][3]);
            *(float2*)&C[(size_t)(crow + mt * 16) * kH + ccol + nt * 8] = v0;
            *(float2*)&C[(size_t)(crow + mt * 16 + 8) * kH + ccol + nt * 8] = v1;
        }
    }
#undef LOADCH
}

// ---------------- SIMT GEMM for the narrow (K=128/256) layers ----------------
template <bool RELU_A>
__global__ __launch_bounds__(256) void gemm128(const float* __restrict__ A,
                                               const float* __restrict__ Bm,
                                               float* __restrict__ Cm, int K) {
    __shared__ float As[32][65];
    __shared__ float Bs[32][128];
    const int tid = threadIdx.x;
    const int row0 = blockIdx.x * 64;
    const int nk = K >> 5;
    const int ar = tid >> 3;
    const int ac = (tid & 7) << 2;
    const int ty = tid >> 5;
    const int tx = tid & 31;
    const int br = tid >> 5;
    const int bc = (tid & 31) << 2;

    const float* Arow0 = A + (size_t)(row0 + ar) * K;
    const float* Arow1 = A + (size_t)(row0 + ar + 32) * K;

    float acc[8][4];
#pragma unroll
    for (int i = 0; i < 8; i++)
#pragma unroll
        for (int j = 0; j < 4; j++) acc[i][j] = 0.f;

    float4 pa0 = *(const float4*)(Arow0 + ac);
    float4 pa1 = *(const float4*)(Arow1 + ac);
    float4 pb0 = *(const float4*)&Bm[(size_t)(br) * kH + bc];
    float4 pb1 = *(const float4*)&Bm[(size_t)(br + 8) * kH + bc];
    float4 pb2 = *(const float4*)&Bm[(size_t)(br + 16) * kH + bc];
    float4 pb3 = *(const float4*)&Bm[(size_t)(br + 24) * kH + bc];

    for (int kt = 0; kt < nk; kt++) {
        __syncthreads();
        if (RELU_A) {
            pa0.x = fmaxf(pa0.x, 0.f); pa0.y = fmaxf(pa0.y, 0.f);
            pa0.z = fmaxf(pa0.z, 0.f); pa0.w = fmaxf(pa0.w, 0.f);
            pa1.x = fmaxf(pa1.x, 0.f); pa1.y = fmaxf(pa1.y, 0.f);
            pa1.z = fmaxf(pa1.z, 0.f); pa1.w = fmaxf(pa1.w, 0.f);
        }
        As[ac + 0][ar] = pa0.x; As[ac + 1][ar] = pa0.y;
        As[ac + 2][ar] = pa0.z; As[ac + 3][ar] = pa0.w;
        As[ac + 0][ar + 32] = pa1.x; As[ac + 1][ar + 32] = pa1.y;
        As[ac + 2][ar + 32] = pa1.z; As[ac + 3][ar + 32] = pa1.w;
        *(float4*)&Bs[br][bc] = pb0;
        *(float4*)&Bs[br + 8][bc] = pb1;
        *(float4*)&Bs[br + 16][bc] = pb2;
        *(float4*)&Bs[br + 24][bc] = pb3;
        __syncthreads();
        if (kt + 1 < nk) {
            int ko = (kt + 1) << 5;
            pa0 = *(const float4*)(Arow0 + ko + ac);
            pa1 = *(const float4*)(Arow1 + ko + ac);
            pb0 = *(const float4*)&Bm[(size_t)(ko + br) * kH + bc];
            pb1 = *(const float4*)&Bm[(size_t)(ko + br + 8) * kH + bc];
            pb2 = *(const float4*)&Bm[(size_t)(ko + br + 16) * kH + bc];
            pb3 = *(const float4*)&Bm[(size_t)(ko + br + 24) * kH + bc];
        }
#pragma unroll
        for (int kk = 0; kk < 32; kk++) {
            float a[8];
#pragma unroll
            for (int i = 0; i < 8; i++) a[i] = As[kk][ty * 8 + i];
            float4 b4 = *(const float4*)&Bs[kk][tx << 2];
#pragma unroll
            for (int i = 0; i < 8; i++) {
                acc[i][0] = fmaf(a[i], b4.x, acc[i][0]);
                acc[i][1] = fmaf(a[i], b4.y, acc[i][1]);
                acc[i][2] = fmaf(a[i], b4.z, acc[i][2]);
                acc[i][3] = fmaf(a[i], b4.w, acc[i][3]);
            }
        }
    }
#pragma unroll
    for (int i = 0; i < 8; i++) {
        float4 o = make_float4(acc[i][0], acc[i][1], acc[i][2], acc[i][3]);
        *(float4*)&Cm[(size_t)(row0 + ty * 8 + i) * kH + (tx << 2)] = o;
    }
}

// ---------------- pooling + MLP + sigmoid ----------------
__global__ void poolMlp(const float* __restrict__ mlpW, const float* __restrict__ mlpb,
                        float* __restrict__ outp) {
    int g = blockIdx.x, f = threadIdx.x;
    const float* base = g_Hb + (size_t)g * kC * kH;
    float s = 0.f, m = 0.f;
    for (int r = 0; r < kC; r++) {
        float v = base[(size_t)r * kH + f];
        v = v > 0.f ? v : 0.f;
        s += v;
        m = v > m ? v : m;
    }
    s *= (1.0f / kC);
    float p0 = s * mlpW[f * 2 + 0] + m * mlpW[(kH + f) * 2 + 0];
    float p1 = s * mlpW[f * 2 + 1] + m * mlpW[(kH + f) * 2 + 1];
    __shared__ float r0[128], r1[128];
    r0[f] = p0; r1[f] = p1;
    __syncthreads();
    for (int st = 64; st > 0; st >>= 1) {
        if (f < st) { r0[f] += r0[f + st]; r1[f] += r1[f + st]; }
        __syncthreads();
    }
    if (f == 0) {
        outp[g * 2 + 0] = 1.f / (1.f + expf(-(r0[0] + mlpb[0])));
        outp[g * 2 + 1] = 1.f / (1.f + expf(-(r1[0] + mlpb[1])));
    }
}

// ---------------- driver ----------------
extern "C" void kernel_launch(void* const* d_in, const int* in_sizes, int n_in,
                              void* d_out, int out_size) {
    const float* x    = (const float*)d_in[0];
    const int*   ei   = (const int*)d_in[1];
    const int*   gid  = (const int*)d_in[2];
    const float* pW   = (const float*)d_in[4];
    const float* pb   = (const float*)d_in[5];
    const float* mW   = (const float*)d_in[6];
    const float* w0   = (const float*)d_in[7];
    const float* w1   = (const float*)d_in[8];
    const float* w2   = (const float*)d_in[9];
    const float* mlpW = (const float*)d_in[10];
    const float* mlpb = (const float*)d_in[11];

    float* out  = (float*)d_out;
    float* adj  = out;
    float* pert = out + kNN;
    float* Mo   = out + 2 * kNN;
    float* pred = Mo + (size_t)kN * kC;
    float* aug  = pred + kB * 2;
    float* xm   = aug + kB * 2;

    float *PA, *XW, *Hb;
    __nv_bfloat16 *adjBF, *pertBF, *XWt;
    cudaGetSymbolAddress((void**)&PA, g_PA);
    cudaGetSymbolAddress((void**)&XW, g_XW);
    cudaGetSymbolAddress((void**)&Hb, g_Hb);
    cudaGetSymbolAddress((void**)&adjBF, g_adjBF);
    cudaGetSymbolAddress((void**)&pertBF, g_pertBF);
    cudaGetSymbolAddress((void**)&XWt, g_XWt);

    const int Z64M = (int)(kNN / 4 / 256);

    zeroBuf<<<Z64M, 256>>>((float4*)adj);
    zeroBuf<<<Z64M, 256>>>((float4*)PA);
    transposeP<<<dim3(kB, kC), 256>>>(pW, gid);
    scatterAdj<<<kE / 256, 256>>>(ei, adj);
    scatterPA<<<kE, 256>>>(ei);
    thresholdPA<<<Z64M, 256>>>(pert, pb, gid);
    cvtBF<<<Z64M, 256>>>((const float4*)adj, (__nv_bfloat162*)adjBF);
    maskK<<<(int)((size_t)kN * kC / 4 / 256), 256>>>(x, mW, gid, Mo, xm);

    dim3 tB(32, 8), tG(kN / 32, kH / 32);

    // ---- predictor on (x, adj) ----
    gemm128<false><<<kN / 64, 256>>>(x, w0, XW, kC);
    transB<<<tG, tB>>>(XW, XWt);
    hmmaGemm<<<kN / 64, 256>>>(adjBF, XWt, Hb);
    gemm128<true><<<kN / 64, 256>>>(Hb, w1, XW, kH);
    transB<<<tG, tB>>>(XW, XWt);
    hmmaGemm<<<kN / 64, 256>>>(adjBF, XWt, Hb);
    gemm128<true><<<kN / 64, 256>>>(Hb, w2, XW, kH);
    transB<<<tG, tB>>>(XW, XWt);
    hmmaGemm<<<kN / 64, 256>>>(adjBF, XWt, Hb);
    poolMlp<<<kB, 128>>>(mlpW, mlpb, pred);

    // ---- predictor on (x_masked, pert_adj) ----
    gemm128<false><<<kN / 64, 256>>>(xm, w0, XW, kC);
    transB<<<tG, tB>>>(XW, XWt);
    hmmaGemm<<<kN / 64, 256>>>(pertBF, XWt, Hb);
    gemm128<true><<<kN / 64, 256>>>(Hb, w1, XW, kH);
    transB<<<tG, tB>>>(XW, XWt);
    hmmaGemm<<<kN / 64, 256>>>(pertBF, XWt, Hb);
    gemm128<true><<<kN / 64, 256>>>(Hb, w2, XW, kH);
    transB<<<tG, tB>>>(XW, XWt);
    hmmaGemm<<<kN / 64, 256>>>(pertBF, XWt, Hb);
    poolMlp<<<kB, 128>>>(mlpW, mlpb, aug);
}

// round 7
// speedup vs baseline: 2.4245x; 1.8339x over previous
#include <cuda_runtime.h>
#include <cuda_bf16.h>
#include <math.h>
#include <stdint.h>

#define kN 8192      // total nodes
#define kC 256       // channels / nodes per graph
#define kB 32        // graphs
#define kH 128       // hidden
#define kE 131072    // edges
#define kNN ((size_t)kN * (size_t)kN)

// ---------------- scratch (static device globals; no allocation) ----------------
__device__ __align__(16) float g_PAT[kNN];                   // 256 MB: PA^T (col-major PA), NOT pre-zeroed
__device__ __align__(16) float g_Pt[kB * kC * kC];           // 8 MB transposed P blocks
__device__ __align__(16) float g_Hb[kN * kH];                // 4 MB  A @ XW
__device__ __align__(16) int   g_cnt[kB * kN];               // 1 MB edges per (stripe, col)
__device__ __align__(16) __nv_bfloat16 g_adjBF[kNN];         // 128 MB adj bf16 (exact)
__device__ __align__(16) __nv_bfloat16 g_pertBF[kNN];        // 128 MB pert bf16 (exact)
__device__ __align__(16) __nv_bfloat16 g_XWt[kH * kN];       // 2 MB  (h@W)^T bf16 (K-major)

__device__ __forceinline__ uint32_t smem_u32(const void* p) {
    uint32_t a;
    asm("{ .reg .u64 t; cvta.to.shared.u64 t, %1; cvt.u32.u64 %0, t; }" : "=r"(a) : "l"(p));
    return a;
}
__device__ __forceinline__ void red_v4(float* addr, float4 v) {
    asm volatile("red.global.add.v4.f32 [%0], {%1,%2,%3,%4};"
                 :: "l"(addr), "f"(v.x), "f"(v.y), "f"(v.z), "f"(v.w) : "memory");
}
__device__ __forceinline__ void red_bf16x2(__nv_bfloat162* addr, __nv_bfloat162 v) {
    uint32_t u = *reinterpret_cast<uint32_t*>(&v);
    asm volatile("red.global.add.noftz.bf16x2 [%0], %1;" :: "l"(addr), "r"(u) : "memory");
}
__device__ __forceinline__ float hard_sig(float v) {
    float s = 1.f / (1.f + expf(-v));
    return (s > 0.5f) ? 1.f : 0.f;
}

// ---------------- utility kernels ----------------
__global__ void zeroBuf(float4* __restrict__ p) {
    p[(size_t)blockIdx.x * blockDim.x + threadIdx.x] = make_float4(0.f, 0.f, 0.f, 0.f);
}
__global__ void transposeP(const float* __restrict__ pW, const int* __restrict__ gid) {
    int b = blockIdx.x, k = blockIdx.y, i = threadIdx.x;
    g_Pt[((size_t)b * kC + k) * kC + i] = pW[(size_t)gid[b] * kC * kC + (size_t)i * kC + k];
}
// per edge: adj f32 +=1, adjBF bf16 +=1, cnt[b][c] +=1
__global__ void scatterEdges(const int* __restrict__ ei, float* __restrict__ adj) {
    int e = blockIdx.x * blockDim.x + threadIdx.x;
    if (e < kE) {
        int r = ei[e], c = ei[kE + e];
        size_t idx = (size_t)r * kN + c;
        atomicAdd(adj + idx, 1.0f);
        __nv_bfloat162 v = (idx & 1) ? __floats2bfloat162_rn(0.f, 1.f)
                                     : __floats2bfloat162_rn(1.f, 0.f);
        red_bf16x2((__nv_bfloat162*)(g_adjBF + (idx & ~(size_t)1)), v);
        atomicAdd(&g_cnt[(r >> 8) * kN + c], 1);
    }
}
// pass 1: cnt==1 -> plain store of Pt row into PAT segment; cnt>1 -> store zeros (pre-red init)
__global__ void scatterPstore(const int* __restrict__ ei) {
    int e = blockIdx.x * 4 + (threadIdx.x >> 6);
    int l = threadIdx.x & 63;
    int r = __ldg(&ei[e]);
    int c = __ldg(&ei[kE + e]);
    int b = r >> 8, k = r & 255;
    int cnt = g_cnt[b * kN + c];
    float4 v = make_float4(0.f, 0.f, 0.f, 0.f);
    if (cnt == 1)
        v = *(const float4*)&g_Pt[((size_t)b * kC + k) * kC + l * 4];
    *(float4*)&g_PAT[(size_t)c * kN + b * kC + l * 4] = v;
}
// pass 2: cnt>1 -> coalesced vector red of Pt row into PAT segment
__global__ void scatterPred(const int* __restrict__ ei) {
    int e = blockIdx.x * 4 + (threadIdx.x >> 6);
    int l = threadIdx.x & 63;
    int r = __ldg(&ei[e]);
    int c = __ldg(&ei[kE + e]);
    int b = r >> 8, k = r & 255;
    if (g_cnt[b * kN + c] > 1) {
        float4 v = *(const float4*)&g_Pt[((size_t)b * kC + k) * kC + l * 4];
        red_v4(&g_PAT[(size_t)c * kN + b * kC + l * 4], v);
    }
}
// transposing threshold: pert[i][c] = hard_sig(PAT[c][i] + diag bias); also bf16 copy.
// Unoccupied (b,c) segments are implicit zeros via g_cnt (PAT never globally zeroed).
__global__ __launch_bounds__(256) void thresholdT(float* __restrict__ pert,
                                                  const float* __restrict__ pb,
                                                  const int* __restrict__ gid) {
    __shared__ float s[32][33];
    const int tx = threadIdx.x, ty = threadIdx.y;   // 32 x 8
    const int c0 = blockIdx.x * 32;
    const int i0 = blockIdx.y * 32;
    const int b = i0 >> 8;
#pragma unroll
    for (int j = 0; j < 4; j++) {
        int cl = ty + j * 8;
        int c = c0 + cl;
        float v = 0.f;
        if (g_cnt[b * kN + c] > 0)
            v = g_PAT[(size_t)c * kN + i0 + tx];
        s[cl][tx] = v;
    }
    __syncthreads();
    const bool diag = (c0 >> 8) == b;
    const int gbase = diag ? (int)(gid[b] * (kC * kC)) : 0;
#pragma unroll
    for (int j = 0; j < 4; j++) {
        int il = ty + j * 8;
        int i = i0 + il;
        float v = s[tx][il];
        if (diag)
            v += pb[(size_t)gbase + (i & 255) * kC + ((c0 + tx) & 255)];
        float o = hard_sig(v);
        pert[(size_t)i * kN + c0 + tx] = o;
        g_pertBF[(size_t)i * kN + c0 + tx] = __float2bfloat16(o);
    }
}
__global__ void maskK(const float* __restrict__ x, const float* __restrict__ mW,
                      const int* __restrict__ gid,
                      float* __restrict__ Mo, float* __restrict__ xm) {
    size_t i4 = (size_t)blockIdx.x * blockDim.x + threadIdx.x;
    size_t e0 = i4 * 4;
    int n = (int)(e0 >> 8);
    int c = (int)(e0 & 255);
    int b = n >> 8;
    float4 w = *(const float4*)&mW[(size_t)gid[b] * kC * kC + (size_t)(n & 255) * kC + c];
    float4 xv = *(const float4*)&x[e0];
    float4 m, o;
    m.x = hard_sig(w.x); m.y = hard_sig(w.y); m.z = hard_sig(w.z); m.w = hard_sig(w.w);
    o.x = m.x * xv.x; o.y = m.y * xv.y; o.z = m.z * xv.z; o.w = m.w * xv.w;
    *(float4*)&Mo[e0] = m;
    *(float4*)&xm[e0] = o;
}

// ---------------- narrow SIMT GEMM: XWt = ((relu?)A @ B)^T in bf16 ----------------
// A [8192 x K] f32, B [K x 128] f32, output g_XWt[n][k] bf16 (K-major for HMMA B).
template <bool RELU_A>
__global__ __launch_bounds__(256) void gemm128(const float* __restrict__ A,
                                               const float* __restrict__ Bm, int K) {
    __shared__ float As[32][65];
    __shared__ float Bs[32][128];
    const int tid = threadIdx.x;
    const int row0 = blockIdx.x * 64;
    const int nk = K >> 5;
    const int ar = tid >> 3;
    const int ac = (tid & 7) << 2;
    const int ty = tid >> 5;
    const int tx = tid & 31;
    const int br = tid >> 5;
    const int bc = (tid & 31) << 2;

    const float* Arow0 = A + (size_t)(row0 + ar) * K;
    const float* Arow1 = A + (size_t)(row0 + ar + 32) * K;

    float acc[8][4];
#pragma unroll
    for (int i = 0; i < 8; i++)
#pragma unroll
        for (int j = 0; j < 4; j++) acc[i][j] = 0.f;

    float4 pa0 = *(const float4*)(Arow0 + ac);
    float4 pa1 = *(const float4*)(Arow1 + ac);
    float4 pb0 = *(const float4*)&Bm[(size_t)(br) * kH + bc];
    float4 pb1 = *(const float4*)&Bm[(size_t)(br + 8) * kH + bc];
    float4 pb2 = *(const float4*)&Bm[(size_t)(br + 16) * kH + bc];
    float4 pb3 = *(const float4*)&Bm[(size_t)(br + 24) * kH + bc];

    for (int kt = 0; kt < nk; kt++) {
        __syncthreads();
        if (RELU_A) {
            pa0.x = fmaxf(pa0.x, 0.f); pa0.y = fmaxf(pa0.y, 0.f);
            pa0.z = fmaxf(pa0.z, 0.f); pa0.w = fmaxf(pa0.w, 0.f);
            pa1.x = fmaxf(pa1.x, 0.f); pa1.y = fmaxf(pa1.y, 0.f);
            pa1.z = fmaxf(pa1.z, 0.f); pa1.w = fmaxf(pa1.w, 0.f);
        }
        As[ac + 0][ar] = pa0.x; As[ac + 1][ar] = pa0.y;
        As[ac + 2][ar] = pa0.z; As[ac + 3][ar] = pa0.w;
        As[ac + 0][ar + 32] = pa1.x; As[ac + 1][ar + 32] = pa1.y;
        As[ac + 2][ar + 32] = pa1.z; As[ac + 3][ar + 32] = pa1.w;
        *(float4*)&Bs[br][bc] = pb0;
        *(float4*)&Bs[br + 8][bc] = pb1;
        *(float4*)&Bs[br + 16][bc] = pb2;
        *(float4*)&Bs[br + 24][bc] = pb3;
        __syncthreads();
        if (kt + 1 < nk) {
            int ko = (kt + 1) << 5;
            pa0 = *(const float4*)(Arow0 + ko + ac);
            pa1 = *(const float4*)(Arow1 + ko + ac);
            pb0 = *(const float4*)&Bm[(size_t)(ko + br) * kH + bc];
            pb1 = *(const float4*)&Bm[(size_t)(ko + br + 8) * kH + bc];
            pb2 = *(const float4*)&Bm[(size_t)(ko + br + 16) * kH + bc];
            pb3 = *(const float4*)&Bm[(size_t)(ko + br + 24) * kH + bc];
        }
#pragma unroll
        for (int kk = 0; kk < 32; kk++) {
            float a[8];
#pragma unroll
            for (int i = 0; i < 8; i++) a[i] = As[kk][ty * 8 + i];
            float4 b4 = *(const float4*)&Bs[kk][tx << 2];
#pragma unroll
            for (int i = 0; i < 8; i++) {
                acc[i][0] = fmaf(a[i], b4.x, acc[i][0]);
                acc[i][1] = fmaf(a[i], b4.y, acc[i][1]);
                acc[i][2] = fmaf(a[i], b4.z, acc[i][2]);
                acc[i][3] = fmaf(a[i], b4.w, acc[i][3]);
            }
        }
    }
    // transposed bf16 epilogue: XWt[col][row0+ty*8 .. +7] as one uint4
#pragma unroll
    for (int j = 0; j < 4; j++) {
        __nv_bfloat162 p0 = __floats2bfloat162_rn(acc[0][j], acc[1][j]);
        __nv_bfloat162 p1 = __floats2bfloat162_rn(acc[2][j], acc[3][j]);
        __nv_bfloat162 p2 = __floats2bfloat162_rn(acc[4][j], acc[5][j]);
        __nv_bfloat162 p3 = __floats2bfloat162_rn(acc[6][j], acc[7][j]);
        uint4 u;
        u.x = *reinterpret_cast<uint32_t*>(&p0);
        u.y = *reinterpret_cast<uint32_t*>(&p1);
        u.z = *reinterpret_cast<uint32_t*>(&p2);
        u.w = *reinterpret_cast<uint32_t*>(&p3);
        *(uint4*)&g_XWt[(size_t)(tx * 4 + j) * kN + row0 + ty * 8] = u;
    }
}

// ---------------- HMMA bf16 GEMM: Hb[8192 x 128] = A[8192 x 8192] @ XWt^T ----------------
#define NKCH (kN / 32)
#define ABUF (64 * 80)
#define BBUF (128 * 80)

__global__ __launch_bounds__(256) void hmmaGemm(const __nv_bfloat16* __restrict__ Abf,
                                                float* __restrict__ C) {
    __shared__ __align__(16) unsigned char smA[2 * ABUF];
    __shared__ __align__(16) unsigned char smB[2 * BBUF];
    const __nv_bfloat16* Bt = g_XWt;
    const int tid = threadIdx.x;
    const int lane = tid & 31, wid = tid >> 5;
    const int wm = wid >> 2, wn = wid & 3;
    const int row0 = blockIdx.x * 64;

    const uint32_t saBase = smem_u32(smA);
    const uint32_t sbBase = smem_u32(smB);

    const int ar = tid >> 2, aseg = tid & 3;
    const __nv_bfloat16* aSrc  = Abf + (size_t)(row0 + ar) * kN + aseg * 8;
    const __nv_bfloat16* bSrc0 = Bt + (size_t)ar * kN + aseg * 8;
    const __nv_bfloat16* bSrc1 = Bt + (size_t)(ar + 64) * kN + aseg * 8;
    const uint32_t aDst  = saBase + ar * 80 + aseg * 16;
    const uint32_t bDst0 = sbBase + ar * 80 + aseg * 16;
    const uint32_t bDst1 = sbBase + (ar + 64) * 80 + aseg * 16;

#define LOADCH(kt, bi) do {                                                           \
        int kk_ = (kt) * 32;                                                          \
        asm volatile("cp.async.cg.shared.global [%0], [%1], 16;"                      \
                     :: "r"(aDst + (bi) * ABUF), "l"(aSrc + kk_) : "memory");         \
        asm volatile("cp.async.cg.shared.global [%0], [%1], 16;"                      \
                     :: "r"(bDst0 + (bi) * BBUF), "l"(bSrc0 + kk_) : "memory");       \
        asm volatile("cp.async.cg.shared.global [%0], [%1], 16;"                      \
                     :: "r"(bDst1 + (bi) * BBUF), "l"(bSrc1 + kk_) : "memory");       \
        asm volatile("cp.async.commit_group;" ::: "memory");                          \
    } while (0)

    float acc[2][4][4];
#pragma unroll
    for (int mt = 0; mt < 2; mt++)
#pragma unroll
        for (int nt = 0; nt < 4; nt++)
#pragma unroll
            for (int q = 0; q < 4; q++) acc[mt][nt][q] = 0.f;

    const int l15 = lane & 15;
    const uint32_t aLm0 = (uint32_t)((wm * 32 + l15) * 80 + ((lane >> 4) & 1) * 16);
    const uint32_t bLmRow = (uint32_t)((wn * 32 + (l15 & 7)) * 80 + ((l15 >> 3) & 1) * 16);

    LOADCH(0, 0);

    for (int kt = 0; kt < NKCH; kt++) {
        const int cur = kt & 1;
        if (kt + 1 < NKCH) {
            LOADCH(kt + 1, cur ^ 1);
            asm volatile("cp.async.wait_group 1;" ::: "memory");
        } else {
            asm volatile("cp.async.wait_group 0;" ::: "memory");
        }
        __syncthreads();

        const uint32_t saB = saBase + cur * ABUF;
        const uint32_t sbB = sbBase + cur * BBUF;
#pragma unroll
        for (int ks = 0; ks < 2; ks++) {
            uint32_t af[2][4];
#pragma unroll
            for (int mt = 0; mt < 2; mt++) {
                uint32_t ad = saB + aLm0 + (uint32_t)(mt * 16 * 80 + ks * 32);
                asm volatile("ldmatrix.sync.aligned.m8n8.x4.shared.b16 {%0,%1,%2,%3}, [%4];"
                             : "=r"(af[mt][0]), "=r"(af[mt][1]), "=r"(af[mt][2]), "=r"(af[mt][3])
                             : "r"(ad));
            }
#pragma unroll
            for (int nt = 0; nt < 4; nt++) {
                uint32_t b0, b1;
                uint32_t bd = sbB + bLmRow + (uint32_t)(nt * 8 * 80 + ks * 32);
                asm volatile("ldmatrix.sync.aligned.m8n8.x2.shared.b16 {%0,%1}, [%2];"
                             : "=r"(b0), "=r"(b1) : "r"(bd));
#pragma unroll
                for (int mt = 0; mt < 2; mt++) {
                    asm volatile(
                        "mma.sync.aligned.m16n8k16.row.col.f32.bf16.bf16.f32 "
                        "{%0,%1,%2,%3}, {%4,%5,%6,%7}, {%8,%9}, {%0,%1,%2,%3};"
                        : "+f"(acc[mt][nt][0]), "+f"(acc[mt][nt][1]),
                          "+f"(acc[mt][nt][2]), "+f"(acc[mt][nt][3])
                        : "r"(af[mt][0]), "r"(af[mt][1]), "r"(af[mt][2]), "r"(af[mt][3]),
                          "r"(b0), "r"(b1));
                }
            }
        }
        __syncthreads();
    }

    const int crow = row0 + wm * 32 + (lane >> 2);
    const int ccol = wn * 32 + (lane & 3) * 2;
#pragma unroll
    for (int mt = 0; mt < 2; mt++) {
#pragma unroll
        for (int nt = 0; nt < 4; nt++) {
            float2 v0 = make_float2(acc[mt][nt][0], acc[mt][nt][1]);
            float2 v1 = make_float2(acc[mt][nt][2], acc[mt][nt][3]);
            *(float2*)&C[(size_t)(crow + mt * 16) * kH + ccol + nt * 8] = v0;
            *(float2*)&C[(size_t)(crow + mt * 16 + 8) * kH + ccol + nt * 8] = v1;
        }
    }
#undef LOADCH
}

// ---------------- pooling + MLP + sigmoid ----------------
__global__ void poolMlp(const float* __restrict__ mlpW, const float* __restrict__ mlpb,
                        float* __restrict__ outp) {
    int g = blockIdx.x, f = threadIdx.x;
    const float* base = g_Hb + (size_t)g * kC * kH;
    float s = 0.f, m = 0.f;
    for (int r = 0; r < kC; r++) {
        float v = base[(size_t)r * kH + f];
        v = v > 0.f ? v : 0.f;
        s += v;
        m = v > m ? v : m;
    }
    s *= (1.0f / kC);
    float p0 = s * mlpW[f * 2 + 0] + m * mlpW[(kH + f) * 2 + 0];
    float p1 = s * mlpW[f * 2 + 1] + m * mlpW[(kH + f) * 2 + 1];
    __shared__ float r0[128], r1[128];
    r0[f] = p0; r1[f] = p1;
    __syncthreads();
    for (int st = 64; st > 0; st >>= 1) {
        if (f < st) { r0[f] += r0[f + st]; r1[f] += r1[f + st]; }
        __syncthreads();
    }
    if (f == 0) {
        outp[g * 2 + 0] = 1.f / (1.f + expf(-(r0[0] + mlpb[0])));
        outp[g * 2 + 1] = 1.f / (1.f + expf(-(r1[0] + mlpb[1])));
    }
}

// ---------------- driver ----------------
extern "C" void kernel_launch(void* const* d_in, const int* in_sizes, int n_in,
                              void* d_out, int out_size) {
    const float* x    = (const float*)d_in[0];
    const int*   ei   = (const int*)d_in[1];
    const int*   gid  = (const int*)d_in[2];
    const float* pW   = (const float*)d_in[4];
    const float* pb   = (const float*)d_in[5];
    const float* mW   = (const float*)d_in[6];
    const float* w0   = (const float*)d_in[7];
    const float* w1   = (const float*)d_in[8];
    const float* w2   = (const float*)d_in[9];
    const float* mlpW = (const float*)d_in[10];
    const float* mlpb = (const float*)d_in[11];

    float* out  = (float*)d_out;
    float* adj  = out;
    float* pert = out + kNN;
    float* Mo   = out + 2 * kNN;
    float* pred = Mo + (size_t)kN * kC;
    float* aug  = pred + kB * 2;
    float* xm   = aug + kB * 2;

    float *Hb;
    __nv_bfloat16 *adjBF, *pertBF;
    int* cnt;
    cudaGetSymbolAddress((void**)&Hb, g_Hb);
    cudaGetSymbolAddress((void**)&adjBF, g_adjBF);
    cudaGetSymbolAddress((void**)&pertBF, g_pertBF);
    cudaGetSymbolAddress((void**)&cnt, g_cnt);

    const int Z64M = (int)(kNN / 4 / 256);        // 256MB f32 as float4
    const int Z32M = (int)(kNN / 8 / 256);        // 128MB bf16 as float4
    const int ZC   = (int)((size_t)kB * kN * 4 / 16 / 256);  // 1MB cnt

    zeroBuf<<<Z64M, 256>>>((float4*)adj);
    zeroBuf<<<Z32M, 256>>>((float4*)adjBF);
    zeroBuf<<<ZC, 256>>>((float4*)cnt);
    transposeP<<<dim3(kB, kC), 256>>>(pW, gid);
    scatterEdges<<<kE / 256, 256>>>(ei, adj);
    scatterPstore<<<kE / 4, 256>>>(ei);
    scatterPred<<<kE / 4, 256>>>(ei);
    thresholdT<<<dim3(kN / 32, kN / 32), dim3(32, 8)>>>(pert, pb, gid);
    maskK<<<(int)((size_t)kN * kC / 4 / 256), 256>>>(x, mW, gid, Mo, xm);

    // ---- predictor on (x, adj) ----
    gemm128<false><<<kN / 64, 256>>>(x, w0, kC);
    hmmaGemm<<<kN / 64, 256>>>(adjBF, Hb);
    gemm128<true><<<kN / 64, 256>>>(Hb, w1, kH);
    hmmaGemm<<<kN / 64, 256>>>(adjBF, Hb);
    gemm128<true><<<kN / 64, 256>>>(Hb, w2, kH);
    hmmaGemm<<<kN / 64, 256>>>(adjBF, Hb);
    poolMlp<<<kB, 128>>>(mlpW, mlpb, pred);

    // ---- predictor on (x_masked, pert_adj) ----
    gemm128<false><<<kN / 64, 256>>>(xm, w0, kC);
    hmmaGemm<<<kN / 64, 256>>>(pertBF, Hb);
    gemm128<true><<<kN / 64, 256>>>(Hb, w1, kH);
    hmmaGemm<<<kN / 64, 256>>>(pertBF, Hb);
    gemm128<true><<<kN / 64, 256>>>(Hb, w2, kH);
    hmmaGemm<<<kN / 64, 256>>>(pertBF, Hb);
    poolMlp<<<kB, 128>>>(mlpW, mlpb, aug);
}

// round 8
// speedup vs baseline: 2.7391x; 1.1298x over previous
#include <cuda_runtime.h>
#include <cuda_bf16.h>
#include <math.h>
#include <stdint.h>

#define kN 8192      // total nodes
#define kC 256       // channels / nodes per graph
#define kB 32        // graphs
#define kH 128       // hidden
#define kE 131072    // edges
#define kNN ((size_t)kN * (size_t)kN)

// ---------------- scratch (static device globals; no allocation) ----------------
__device__ __align__(16) float g_PAT[kNN];                   // 256 MB: PA^T, lazily initialized
__device__ __align__(16) float g_Pt[kB * kC * kC];           // 8 MB transposed P blocks
__device__ __align__(16) float g_Hb[kN * kH];                // 4 MB  A @ XW (f32, for pool)
__device__ __align__(16) int   g_cnt[kB * kN];               // 1 MB edges per (stripe, col)
__device__ __align__(16) __nv_bfloat16 g_adjBF[kNN];         // 128 MB adj bf16 (exact)
__device__ __align__(16) __nv_bfloat16 g_pertBF[kNN];        // 128 MB pert bf16 (exact)
__device__ __align__(16) __nv_bfloat16 g_XWt[kH * kN];       // 2 MB  (h@W)^T bf16 (K-major)
__device__ __align__(16) __nv_bfloat16 g_xBF[kN * kC];       // 4 MB  bf16(x)
__device__ __align__(16) __nv_bfloat16 g_xmBF[kN * kC];      // 4 MB  bf16(x_masked)
__device__ __align__(16) __nv_bfloat16 g_HbBF[kN * kH];      // 2 MB  bf16(relu(Hb))
__device__ __align__(16) __nv_bfloat16 g_wT[3][kC * kH];     // weights^T bf16 (K-major)

__device__ __forceinline__ uint32_t smem_u32(const void* p) {
    uint32_t a;
    asm("{ .reg .u64 t; cvta.to.shared.u64 t, %1; cvt.u32.u64 %0, t; }" : "=r"(a) : "l"(p));
    return a;
}
__device__ __forceinline__ void red_v4(float* addr, float4 v) {
    asm volatile("red.global.add.v4.f32 [%0], {%1,%2,%3,%4};"
                 :: "l"(addr), "f"(v.x), "f"(v.y), "f"(v.z), "f"(v.w) : "memory");
}
__device__ __forceinline__ void red_bf16x2(__nv_bfloat162* addr, __nv_bfloat162 v) {
    uint32_t u = *reinterpret_cast<uint32_t*>(&v);
    asm volatile("red.global.add.noftz.bf16x2 [%0], %1;" :: "l"(addr), "r"(u) : "memory");
}
__device__ __forceinline__ float hard_sig(float v) {
    float s = 1.f / (1.f + expf(-v));
    return (s > 0.5f) ? 1.f : 0.f;
}

// ---------------- utility kernels ----------------
__global__ void zeroBuf(float4* __restrict__ p) {
    p[(size_t)blockIdx.x * blockDim.x + threadIdx.x] = make_float4(0.f, 0.f, 0.f, 0.f);
}
// tiled transpose of selected P blocks: g_Pt[b][k][i] = pW[gid[b]][i][k]
__global__ void transposeP(const float* __restrict__ pW, const int* __restrict__ gid) {
    __shared__ float t[32][33];
    int b = blockIdx.z;
    int i0 = blockIdx.x * 32, k0 = blockIdx.y * 32;
    int tx = threadIdx.x, ty = threadIdx.y;  // 32 x 8
    const float* src = pW + (size_t)gid[b] * kC * kC;
#pragma unroll
    for (int j = 0; j < 4; j++)
        t[ty + j * 8][tx] = src[(size_t)(i0 + ty + j * 8) * kC + k0 + tx];
    __syncthreads();
#pragma unroll
    for (int j = 0; j < 4; j++)
        g_Pt[(size_t)b * kC * kC + (size_t)(k0 + ty + j * 8) * kC + i0 + tx] = t[tx][ty + j * 8];
}
// per edge: adj f32 +=1, adjBF bf16 +=1, cnt[b][c] +=1
__global__ void scatterEdges(const int* __restrict__ ei, float* __restrict__ adj) {
    int e = blockIdx.x * blockDim.x + threadIdx.x;
    if (e < kE) {
        int r = ei[e], c = ei[kE + e];
        size_t idx = (size_t)r * kN + c;
        atomicAdd(adj + idx, 1.0f);
        __nv_bfloat162 v = (idx & 1) ? __floats2bfloat162_rn(0.f, 1.f)
                                     : __floats2bfloat162_rn(1.f, 0.f);
        red_bf16x2((__nv_bfloat162*)(g_adjBF + (idx & ~(size_t)1)), v);
        atomicAdd(&g_cnt[(r >> 8) * kN + c], 1);
    }
}
// pass 1: cnt==1 -> plain store of Pt row; cnt>1 -> store zeros (pre-red init)
__global__ void scatterPstore(const int* __restrict__ ei) {
    int e = blockIdx.x * 4 + (threadIdx.x >> 6);
    int l = threadIdx.x & 63;
    int r = __ldg(&ei[e]);
    int c = __ldg(&ei[kE + e]);
    int b = r >> 8, k = r & 255;
    int cnt = g_cnt[b * kN + c];
    float4 v = make_float4(0.f, 0.f, 0.f, 0.f);
    if (cnt == 1)
        v = *(const float4*)&g_Pt[((size_t)b * kC + k) * kC + l * 4];
    *(float4*)&g_PAT[(size_t)c * kN + b * kC + l * 4] = v;
}
// pass 2: cnt>1 -> coalesced vector red
__global__ void scatterPred(const int* __restrict__ ei) {
    int e = blockIdx.x * 4 + (threadIdx.x >> 6);
    int l = threadIdx.x & 63;
    int r = __ldg(&ei[e]);
    int c = __ldg(&ei[kE + e]);
    int b = r >> 8, k = r & 255;
    if (g_cnt[b * kN + c] > 1) {
        float4 v = *(const float4*)&g_Pt[((size_t)b * kC + k) * kC + l * 4];
        red_v4(&g_PAT[(size_t)c * kN + b * kC + l * 4], v);
    }
}
// transposing threshold: pert[i][c] = hard_sig(PAT[c][i] + diag bias); also bf16 copy.
__global__ __launch_bounds__(256) void thresholdT(float* __restrict__ pert,
                                                  const float* __restrict__ pb,
                                                  const int* __restrict__ gid) {
    __shared__ float s[32][33];
    const int tx = threadIdx.x, ty = threadIdx.y;   // 32 x 8
    const int c0 = blockIdx.x * 32;
    const int i0 = blockIdx.y * 32;
    const int b = i0 >> 8;
#pragma unroll
    for (int j = 0; j < 4; j++) {
        int cl = ty + j * 8;
        int c = c0 + cl;
        float v = 0.f;
        if (g_cnt[b * kN + c] > 0)
            v = g_PAT[(size_t)c * kN + i0 + tx];
        s[cl][tx] = v;
    }
    __syncthreads();
    const bool diag = (c0 >> 8) == b;
    const int gbase = diag ? (int)(gid[b] * (kC * kC)) : 0;
#pragma unroll
    for (int j = 0; j < 4; j++) {
        int il = ty + j * 8;
        int i = i0 + il;
        float v = s[tx][il];
        if (diag)
            v += pb[(size_t)gbase + (i & 255) * kC + ((c0 + tx) & 255)];
        float o = hard_sig(v);
        pert[(size_t)i * kN + c0 + tx] = o;
        g_pertBF[(size_t)i * kN + c0 + tx] = __float2bfloat16(o);
    }
}
// M = hard(sigmoid(mask_W)), xm = M*x; also xmBF = bf16(xm)
__global__ void maskK(const float* __restrict__ x, const float* __restrict__ mW,
                      const int* __restrict__ gid,
                      float* __restrict__ Mo, float* __restrict__ xm) {
    size_t i4 = (size_t)blockIdx.x * blockDim.x + threadIdx.x;
    size_t e0 = i4 * 4;
    int n = (int)(e0 >> 8);
    int c = (int)(e0 & 255);
    int b = n >> 8;
    float4 w = *(const float4*)&mW[(size_t)gid[b] * kC * kC + (size_t)(n & 255) * kC + c];
    float4 xv = *(const float4*)&x[e0];
    float4 m, o;
    m.x = hard_sig(w.x); m.y = hard_sig(w.y); m.z = hard_sig(w.z); m.w = hard_sig(w.w);
    o.x = m.x * xv.x; o.y = m.y * xv.y; o.z = m.z * xv.z; o.w = m.w * xv.w;
    *(float4*)&Mo[e0] = m;
    *(float4*)&xm[e0] = o;
    __nv_bfloat162* d = (__nv_bfloat162*)g_xmBF;
    d[i4 * 2]     = __floats2bfloat162_rn(o.x, o.y);
    d[i4 * 2 + 1] = __floats2bfloat162_rn(o.z, o.w);
}
__global__ void cvtX(const float4* __restrict__ src, __nv_bfloat162* __restrict__ dst) {
    size_t i = (size_t)blockIdx.x * blockDim.x + threadIdx.x;
    float4 v = src[i];
    dst[2 * i]     = __floats2bfloat162_rn(v.x, v.y);
    dst[2 * i + 1] = __floats2bfloat162_rn(v.z, v.w);
}
// WT[n][k] = bf16(W[k][n]); W is [K x 128]
__global__ void cvtWT(const float* __restrict__ W, __nv_bfloat16* __restrict__ WT, int K) {
    int idx = blockIdx.x * 256 + threadIdx.x;
    int n = idx / K, k = idx - n * K;
    WT[idx] = __float2bfloat16(W[(size_t)k * kH + n]);
}

// ---------------- shared HMMA building blocks ----------------
#define ABUF (64 * 80)      // 5120 B per A stage
#define BBUF (128 * 80)     // 10240 B per B stage

#define HMMA_FRAG_DECL                                                                 \
    float acc[2][4][4];                                                                \
    _Pragma("unroll") for (int mt = 0; mt < 2; mt++)                                   \
    _Pragma("unroll") for (int nt = 0; nt < 4; nt++)                                   \
    _Pragma("unroll") for (int q = 0; q < 4; q++) acc[mt][nt][q] = 0.f;

#define HMMA_COMPUTE(saB, sbB)                                                         \
    _Pragma("unroll")                                                                  \
    for (int ks = 0; ks < 2; ks++) {                                                   \
        uint32_t af[2][4];                                                             \
        _Pragma("unroll")                                                              \
        for (int mt = 0; mt < 2; mt++) {                                               \
            uint32_t ad = (saB) + aLm0 + (uint32_t)(mt * 16 * 80 + ks * 32);           \
            asm volatile("ldmatrix.sync.aligned.m8n8.x4.shared.b16 {%0,%1,%2,%3}, [%4];" \
                         : "=r"(af[mt][0]), "=r"(af[mt][1]), "=r"(af[mt][2]),          \
                           "=r"(af[mt][3]) : "r"(ad));                                 \
        }                                                                              \
        _Pragma("unroll")                                                              \
        for (int nt = 0; nt < 4; nt++) {                                               \
            uint32_t b0, b1;                                                           \
            uint32_t bd = (sbB) + bLmRow + (uint32_t)(nt * 8 * 80 + ks * 32);          \
            asm volatile("ldmatrix.sync.aligned.m8n8.x2.shared.b16 {%0,%1}, [%2];"     \
                         : "=r"(b0), "=r"(b1) : "r"(bd));                              \
            _Pragma("unroll")                                                          \
            for (int mt = 0; mt < 2; mt++) {                                           \
                asm volatile(                                                          \
                    "mma.sync.aligned.m16n8k16.row.col.f32.bf16.bf16.f32 "             \
                    "{%0,%1,%2,%3}, {%4,%5,%6,%7}, {%8,%9}, {%0,%1,%2,%3};"            \
                    : "+f"(acc[mt][nt][0]), "+f"(acc[mt][nt][1]),                      \
                      "+f"(acc[mt][nt][2]), "+f"(acc[mt][nt][3])                       \
                    : "r"(af[mt][0]), "r"(af[mt][1]), "r"(af[mt][2]), "r"(af[mt][3]),  \
                      "r"(b0), "r"(b1));                                               \
            }                                                                          \
        }                                                                              \
    }

#define LOADCH_GEN(kt, bi, ldA, ldB) do {                                              \
        int kk_ = (kt) * 32;                                                           \
        asm volatile("cp.async.cg.shared.global [%0], [%1], 16;"                       \
                     :: "r"(aDst + (bi) * ABUF), "l"(aSrc + kk_) : "memory");          \
        asm volatile("cp.async.cg.shared.global [%0], [%1], 16;"                       \
                     :: "r"(bDst0 + (bi) * BBUF), "l"(bSrc0 + kk_) : "memory");        \
        asm volatile("cp.async.cg.shared.global [%0], [%1], 16;"                       \
                     :: "r"(bDst1 + (bi) * BBUF), "l"(bSrc1 + kk_) : "memory");        \
        asm volatile("cp.async.commit_group;" ::: "memory");                           \
    } while (0)

// ---------------- big HMMA: Hb = A[8192x8192]bf16 @ g_XWt^T ; 3-stage pipeline ----------------
#define NKCH (kN / 32)
__global__ __launch_bounds__(256) void hmmaGemm(const __nv_bfloat16* __restrict__ Abf,
                                                float* __restrict__ C) {
    __shared__ __align__(16) unsigned char smA[3 * ABUF];
    __shared__ __align__(16) unsigned char smB[3 * BBUF];
    const __nv_bfloat16* Bt = g_XWt;
    const int tid = threadIdx.x;
    const int lane = tid & 31, wid = tid >> 5;
    const int wm = wid >> 2, wn = wid & 3;
    const int row0 = blockIdx.x * 64;

    const uint32_t saBase = smem_u32(smA);
    const uint32_t sbBase = smem_u32(smB);

    const int ar = tid >> 2, aseg = tid & 3;
    const __nv_bfloat16* aSrc  = Abf + (size_t)(row0 + ar) * kN + aseg * 8;
    const __nv_bfloat16* bSrc0 = Bt + (size_t)ar * kN + aseg * 8;
    const __nv_bfloat16* bSrc1 = Bt + (size_t)(ar + 64) * kN + aseg * 8;
    const uint32_t aDst  = saBase + ar * 80 + aseg * 16;
    const uint32_t bDst0 = sbBase + ar * 80 + aseg * 16;
    const uint32_t bDst1 = sbBase + (ar + 64) * 80 + aseg * 16;

    HMMA_FRAG_DECL;

    const int l15 = lane & 15;
    const uint32_t aLm0 = (uint32_t)((wm * 32 + l15) * 80 + ((lane >> 4) & 1) * 16);
    const uint32_t bLmRow = (uint32_t)((wn * 32 + (l15 & 7)) * 80 + ((l15 >> 3) & 1) * 16);

    LOADCH_GEN(0, 0, kN, kN);
    LOADCH_GEN(1, 1, kN, kN);

    for (int kt = 0; kt < NKCH; kt++) {
        const int cur = kt % 3;
        if (kt + 2 < NKCH) {
            LOADCH_GEN(kt + 2, (kt + 2) % 3, kN, kN);
            asm volatile("cp.async.wait_group 2;" ::: "memory");
        } else if (kt + 1 < NKCH) {
            asm volatile("cp.async.wait_group 1;" ::: "memory");
        } else {
            asm volatile("cp.async.wait_group 0;" ::: "memory");
        }
        __syncthreads();
        HMMA_COMPUTE(saBase + cur * ABUF, sbBase + cur * BBUF);
        __syncthreads();
    }

    // epilogue: Hb f32 + HbBF = bf16(relu(.))
    const int crow = row0 + wm * 32 + (lane >> 2);
    const int ccol = wn * 32 + (lane & 3) * 2;
#pragma unroll
    for (int mt = 0; mt < 2; mt++) {
#pragma unroll
        for (int nt = 0; nt < 4; nt++) {
            float2 v0 = make_float2(acc[mt][nt][0], acc[mt][nt][1]);
            float2 v1 = make_float2(acc[mt][nt][2], acc[mt][nt][3]);
            size_t o0 = (size_t)(crow + mt * 16) * kH + ccol + nt * 8;
            size_t o1 = (size_t)(crow + mt * 16 + 8) * kH + ccol + nt * 8;
            *(float2*)&C[o0] = v0;
            *(float2*)&C[o1] = v1;
            __nv_bfloat162 r0 = __floats2bfloat162_rn(fmaxf(v0.x, 0.f), fmaxf(v0.y, 0.f));
            __nv_bfloat162 r1 = __floats2bfloat162_rn(fmaxf(v1.x, 0.f), fmaxf(v1.y, 0.f));
            *(__nv_bfloat162*)&g_HbBF[o0] = r0;
            *(__nv_bfloat162*)&g_HbBF[o1] = r1;
        }
    }
}

// ---------------- narrow HMMA: g_XWt = (A[8192xK]bf16 @ WT^T)^T bf16 ----------------
template <int K>
__global__ __launch_bounds__(256) void hmmaNarrow(const __nv_bfloat16* __restrict__ Abf,
                                                  const __nv_bfloat16* __restrict__ Bt) {
    __shared__ __align__(16) unsigned char smA[2 * ABUF];
    __shared__ __align__(16) unsigned char smB[2 * BBUF];
    __shared__ __align__(16) __nv_bfloat16 Ts[kH * 72];   // staging: [col][row] stride 72
    const int tid = threadIdx.x;
    const int lane = tid & 31, wid = tid >> 5;
    const int wm = wid >> 2, wn = wid & 3;
    const int row0 = blockIdx.x * 64;
    const int nch = K / 32;

    const uint32_t saBase = smem_u32(smA);
    const uint32_t sbBase = smem_u32(smB);

    const int ar = tid >> 2, aseg = tid & 3;
    const __nv_bfloat16* aSrc  = Abf + (size_t)(row0 + ar) * K + aseg * 8;
    const __nv_bfloat16* bSrc0 = Bt + (size_t)ar * K + aseg * 8;
    const __nv_bfloat16* bSrc1 = Bt + (size_t)(ar + 64) * K + aseg * 8;
    const uint32_t aDst  = saBase + ar * 80 + aseg * 16;
    const uint32_t bDst0 = sbBase + ar * 80 + aseg * 16;
    const uint32_t bDst1 = sbBase + (ar + 64) * 80 + aseg * 16;

    HMMA_FRAG_DECL;

    const int l15 = lane & 15;
    const uint32_t aLm0 = (uint32_t)((wm * 32 + l15) * 80 + ((lane >> 4) & 1) * 16);
    const uint32_t bLmRow = (uint32_t)((wn * 32 + (l15 & 7)) * 80 + ((l15 >> 3) & 1) * 16);

    LOADCH_GEN(0, 0, K, K);
    for (int kt = 0; kt < nch; kt++) {
        const int cur = kt & 1;
        if (kt + 1 < nch) {
            LOADCH_GEN(kt + 1, cur ^ 1, K, K);
            asm volatile("cp.async.wait_group 1;" ::: "memory");
        } else {
            asm volatile("cp.async.wait_group 0;" ::: "memory");
        }
        __syncthreads();
        HMMA_COMPUTE(saBase + cur * ABUF, sbBase + cur * BBUF);
        __syncthreads();
    }

    // stage transposed bf16 tile: Ts[col][row-row0]
    const int rloc = wm * 32 + (lane >> 2);
    const int ccol = wn * 32 + (lane & 3) * 2;
#pragma unroll
    for (int mt = 0; mt < 2; mt++) {
#pragma unroll
        for (int nt = 0; nt < 4; nt++) {
            int c = ccol + nt * 8;
            Ts[(c + 0) * 72 + rloc + mt * 16]     = __float2bfloat16(acc[mt][nt][0]);
            Ts[(c + 1) * 72 + rloc + mt * 16]     = __float2bfloat16(acc[mt][nt][1]);
            Ts[(c + 0) * 72 + rloc + mt * 16 + 8] = __float2bfloat16(acc[mt][nt][2]);
            Ts[(c + 1) * 72 + rloc + mt * 16 + 8] = __float2bfloat16(acc[mt][nt][3]);
        }
    }
    __syncthreads();
    // coalesced write-out: thread -> (col = tid/2, half = tid&1), 32 bf16 each
    {
        int col = tid >> 1, half = tid & 1;
        const uint4* src = (const uint4*)&Ts[col * 72 + half * 32];
        uint4* dst = (uint4*)&g_XWt[(size_t)col * kN + row0 + half * 32];
#pragma unroll
        for (int q = 0; q < 4; q++) dst[q] = src[q];
    }
}

// ---------------- pooling + MLP + sigmoid ----------------
__global__ void poolMlp(const float* __restrict__ mlpW, const float* __restrict__ mlpb,
                        float* __restrict__ outp) {
    int g = blockIdx.x, f = threadIdx.x;
    const float* base = g_Hb + (size_t)g * kC * kH;
    float s = 0.f, m = 0.f;
    for (int r = 0; r < kC; r++) {
        float v = base[(size_t)r * kH + f];
        v = v > 0.f ? v : 0.f;
        s += v;
        m = v > m ? v : m;
    }
    s *= (1.0f / kC);
    float p0 = s * mlpW[f * 2 + 0] + m * mlpW[(kH + f) * 2 + 0];
    float p1 = s * mlpW[f * 2 + 1] + m * mlpW[(kH + f) * 2 + 1];
    __shared__ float r0[128], r1[128];
    r0[f] = p0; r1[f] = p1;
    __syncthreads();
    for (int st = 64; st > 0; st >>= 1) {
        if (f < st) { r0[f] += r0[f + st]; r1[f] += r1[f + st]; }
        __syncthreads();
    }
    if (f == 0) {
        outp[g * 2 + 0] = 1.f / (1.f + expf(-(r0[0] + mlpb[0])));
        outp[g * 2 + 1] = 1.f / (1.f + expf(-(r1[0] + mlpb[1])));
    }
}

// ---------------- driver ----------------
extern "C" void kernel_launch(void* const* d_in, const int* in_sizes, int n_in,
                              void* d_out, int out_size) {
    const float* x    = (const float*)d_in[0];
    const int*   ei   = (const int*)d_in[1];
    const int*   gid  = (const int*)d_in[2];
    const float* pW   = (const float*)d_in[4];
    const float* pb   = (const float*)d_in[5];
    const float* mW   = (const float*)d_in[6];
    const float* w0   = (const float*)d_in[7];
    const float* w1   = (const float*)d_in[8];
    const float* w2   = (const float*)d_in[9];
    const float* mlpW = (const float*)d_in[10];
    const float* mlpb = (const float*)d_in[11];

    float* out  = (float*)d_out;
    float* adj  = out;
    float* pert = out + kNN;
    float* Mo   = out + 2 * kNN;
    float* pred = Mo + (size_t)kN * kC;
    float* aug  = pred + kB * 2;
    float* xm   = aug + kB * 2;

    float *Hb;
    __nv_bfloat16 *adjBF, *pertBF, *xBF, *xmBF, *HbBF, *wT;
    int* cnt;
    cudaGetSymbolAddress((void**)&Hb, g_Hb);
    cudaGetSymbolAddress((void**)&adjBF, g_adjBF);
    cudaGetSymbolAddress((void**)&pertBF, g_pertBF);
    cudaGetSymbolAddress((void**)&xBF, g_xBF);
    cudaGetSymbolAddress((void**)&xmBF, g_xmBF);
    cudaGetSymbolAddress((void**)&HbBF, g_HbBF);
    cudaGetSymbolAddress((void**)&wT, g_wT);
    cudaGetSymbolAddress((void**)&cnt, g_cnt);
    __nv_bfloat16* wT0 = wT;
    __nv_bfloat16* wT1 = wT + kC * kH;
    __nv_bfloat16* wT2 = wT + 2 * kC * kH;

    const int Z64M = (int)(kNN / 4 / 256);
    const int Z32M = (int)(kNN / 8 / 256);
    const int ZC   = (int)((size_t)kB * kN * 4 / 16 / 256);

    zeroBuf<<<Z64M, 256>>>((float4*)adj);
    zeroBuf<<<Z32M, 256>>>((float4*)adjBF);
    zeroBuf<<<ZC, 256>>>((float4*)cnt);
    transposeP<<<dim3(8, 8, kB), dim3(32, 8)>>>(pW, gid);
    scatterEdges<<<kE / 256, 256>>>(ei, adj);
    scatterPstore<<<kE / 4, 256>>>(ei);
    scatterPred<<<kE / 4, 256>>>(ei);
    thresholdT<<<dim3(kN / 32, kN / 32), dim3(32, 8)>>>(pert, pb, gid);
    maskK<<<(int)((size_t)kN * kC / 4 / 256), 256>>>(x, mW, gid, Mo, xm);
    cvtX<<<(int)((size_t)kN * kC / 4 / 256), 256>>>((const float4*)x, (__nv_bfloat162*)xBF);
    cvtWT<<<kC * kH / 256, 256>>>(w0, wT0, kC);
    cvtWT<<<kH * kH / 256, 256>>>(w1, wT1, kH);
    cvtWT<<<kH * kH / 256, 256>>>(w2, wT2, kH);

    // ---- predictor on (x, adj) ----
    hmmaNarrow<kC><<<kN / 64, 256>>>(xBF, wT0);
    hmmaGemm<<<kN / 64, 256>>>(adjBF, Hb);
    hmmaNarrow<kH><<<kN / 64, 256>>>(HbBF, wT1);
    hmmaGemm<<<kN / 64, 256>>>(adjBF, Hb);
    hmmaNarrow<kH><<<kN / 64, 256>>>(HbBF, wT2);
    hmmaGemm<<<kN / 64, 256>>>(adjBF, Hb);
    poolMlp<<<kB, 128>>>(mlpW, mlpb, pred);

    // ---- predictor on (x_masked, pert_adj) ----
    hmmaNarrow<kC><<<kN / 64, 256>>>(xmBF, wT0);
    hmmaGemm<<<kN / 64, 256>>>(pertBF, Hb);
    hmmaNarrow<kH><<<kN / 64, 256>>>(HbBF, wT1);
    hmmaGemm<<<kN / 64, 256>>>(pertBF, Hb);
    hmmaNarrow<kH><<<kN / 64, 256>>>(HbBF, wT2);
    hmmaGemm<<<kN / 64, 256>>>(pertBF, Hb);
    poolMlp<<<kB, 128>>>(mlpW, mlpb, aug);
}

// round 9
// speedup vs baseline: 3.5633x; 1.3009x over previous
#include <cuda_runtime.h>
#include <cuda_bf16.h>
#include <math.h>
#include <stdint.h>

#define kN 8192      // total nodes
#define kC 256       // channels / nodes per graph
#define kB 32        // graphs
#define kH 128       // hidden
#define kE 131072    // edges
#define kNN ((size_t)kN * (size_t)kN)

// ---------------- scratch (static device globals; no allocation) ----------------
__device__ __align__(16) float g_PAT[kNN];                   // 256 MB: PA^T, lazily initialized
__device__ __align__(16) float g_Pt[kB * kC * kC];           // 8 MB transposed P blocks
__device__ __align__(16) float g_Hb[kN * kH];                // 4 MB  A @ XW (f32, for pool)
__device__ __align__(16) int   g_cnt[kB * kN];               // 1 MB edges per (stripe, col)
__device__ __align__(16) __nv_bfloat16 g_pertBF[kNN];        // 128 MB pert bf16 (exact)
__device__ __align__(16) __nv_bfloat16 g_XWt[kH * kN];       // 2 MB (h@W)^T bf16 (K-major)
__device__ __align__(16) __nv_bfloat16 g_XWrm[kN * kH];      // 2 MB h@W row-major bf16
__device__ __align__(16) __nv_bfloat16 g_xBF[kN * kC];       // 4 MB bf16(x)
__device__ __align__(16) __nv_bfloat16 g_xmBF[kN * kC];      // 4 MB bf16(x_masked)
__device__ __align__(16) __nv_bfloat16 g_HbBF[kN * kH];      // 2 MB bf16(relu(Hb))
__device__ __align__(16) __nv_bfloat16 g_wT[3][kC * kH];     // weights^T bf16 (K-major)
// CSR for adj
__device__ __align__(16) int g_rowCnt[kN];
__device__ __align__(16) int g_rowPtr[kN];
__device__ __align__(16) int g_rowFill[kN];
__device__ __align__(16) int g_rowCol[kE];

__device__ __forceinline__ uint32_t smem_u32(const void* p) {
    uint32_t a;
    asm("{ .reg .u64 t; cvta.to.shared.u64 t, %1; cvt.u32.u64 %0, t; }" : "=r"(a) : "l"(p));
    return a;
}
__device__ __forceinline__ void red_v4(float* addr, float4 v) {
    asm volatile("red.global.add.v4.f32 [%0], {%1,%2,%3,%4};"
                 :: "l"(addr), "f"(v.x), "f"(v.y), "f"(v.z), "f"(v.w) : "memory");
}
__device__ __forceinline__ float hard_sig(float v) {
    float s = 1.f / (1.f + expf(-v));
    return (s > 0.5f) ? 1.f : 0.f;
}

// ---------------- utility kernels ----------------
__global__ void zeroBuf(float4* __restrict__ p) {
    p[(size_t)blockIdx.x * blockDim.x + threadIdx.x] = make_float4(0.f, 0.f, 0.f, 0.f);
}
__global__ void transposeP(const float* __restrict__ pW, const int* __restrict__ gid) {
    __shared__ float t[32][33];
    int b = blockIdx.z;
    int i0 = blockIdx.x * 32, k0 = blockIdx.y * 32;
    int tx = threadIdx.x, ty = threadIdx.y;  // 32 x 8
    const float* src = pW + (size_t)gid[b] * kC * kC;
#pragma unroll
    for (int j = 0; j < 4; j++)
        t[ty + j * 8][tx] = src[(size_t)(i0 + ty + j * 8) * kC + k0 + tx];
    __syncthreads();
#pragma unroll
    for (int j = 0; j < 4; j++)
        g_Pt[(size_t)b * kC * kC + (size_t)(k0 + ty + j * 8) * kC + i0 + tx] = t[tx][ty + j * 8];
}
// per edge: adj f32 +=1, cnt[b][c] +=1, rowCnt[r] +=1
__global__ void scatterEdges(const int* __restrict__ ei, float* __restrict__ adj) {
    int e = blockIdx.x * blockDim.x + threadIdx.x;
    if (e < kE) {
        int r = ei[e], c = ei[kE + e];
        atomicAdd(adj + (size_t)r * kN + c, 1.0f);
        atomicAdd(&g_cnt[(r >> 8) * kN + c], 1);
        atomicAdd(&g_rowCnt[r], 1);
    }
}
// single-block exclusive scan over rowCnt -> rowPtr, rowFill
__global__ void scanRows() {
    __shared__ int s[1024];
    __shared__ int carry;
    int tid = threadIdx.x;
    if (tid == 0) carry = 0;
    __syncthreads();
    for (int ch = 0; ch < kN / 1024; ch++) {
        int i = ch * 1024 + tid;
        int v = g_rowCnt[i];
        s[tid] = v;
        __syncthreads();
        for (int st = 1; st < 1024; st <<= 1) {
            int t = (tid >= st) ? s[tid - st] : 0;
            __syncthreads();
            s[tid] += t;
            __syncthreads();
        }
        int excl = s[tid] - v + carry;
        g_rowPtr[i] = excl;
        g_rowFill[i] = excl;
        __syncthreads();
        if (tid == 1023) carry += s[1023];
        __syncthreads();
    }
}
__global__ void fillCSR(const int* __restrict__ ei) {
    int e = blockIdx.x * blockDim.x + threadIdx.x;
    if (e < kE) {
        int r = ei[e], c = ei[kE + e];
        int pos = atomicAdd(&g_rowFill[r], 1);
        g_rowCol[pos] = c;
    }
}
// SpMM: Hb[r,:] = sum_{edges (r,c)} XWrm[c,:]; also HbBF = bf16(relu)
__global__ __launch_bounds__(128) void spmmCSR() {
    int r = blockIdx.x, f = threadIdx.x;
    int base = g_rowPtr[r];
    int nnz = g_rowCnt[r];
    float acc = 0.f;
    int j = 0;
    for (; j + 4 <= nnz; j += 4) {
        int c0 = __ldg(&g_rowCol[base + j]);
        int c1 = __ldg(&g_rowCol[base + j + 1]);
        int c2 = __ldg(&g_rowCol[base + j + 2]);
        int c3 = __ldg(&g_rowCol[base + j + 3]);
        float v0 = __bfloat162float(g_XWrm[(size_t)c0 * kH + f]);
        float v1 = __bfloat162float(g_XWrm[(size_t)c1 * kH + f]);
        float v2 = __bfloat162float(g_XWrm[(size_t)c2 * kH + f]);
        float v3 = __bfloat162float(g_XWrm[(size_t)c3 * kH + f]);
        acc += v0 + v1 + v2 + v3;
    }
    for (; j < nnz; j++) {
        int c = __ldg(&g_rowCol[base + j]);
        acc += __bfloat162float(g_XWrm[(size_t)c * kH + f]);
    }
    g_Hb[(size_t)r * kH + f] = acc;
    g_HbBF[(size_t)r * kH + f] = __float2bfloat16(fmaxf(acc, 0.f));
}
// pass 1: cnt==1 -> plain store of Pt row; cnt>1 -> store zeros (pre-red init)
__global__ void scatterPstore(const int* __restrict__ ei) {
    int e = blockIdx.x * 4 + (threadIdx.x >> 6);
    int l = threadIdx.x & 63;
    int r = __ldg(&ei[e]);
    int c = __ldg(&ei[kE + e]);
    int b = r >> 8, k = r & 255;
    int cnt = g_cnt[b * kN + c];
    float4 v = make_float4(0.f, 0.f, 0.f, 0.f);
    if (cnt == 1)
        v = *(const float4*)&g_Pt[((size_t)b * kC + k) * kC + l * 4];
    *(float4*)&g_PAT[(size_t)c * kN + b * kC + l * 4] = v;
}
// pass 2: cnt>1 -> coalesced vector red
__global__ void scatterPred(const int* __restrict__ ei) {
    int e = blockIdx.x * 4 + (threadIdx.x >> 6);
    int l = threadIdx.x & 63;
    int r = __ldg(&ei[e]);
    int c = __ldg(&ei[kE + e]);
    int b = r >> 8, k = r & 255;
    if (g_cnt[b * kN + c] > 1) {
        float4 v = *(const float4*)&g_Pt[((size_t)b * kC + k) * kC + l * 4];
        red_v4(&g_PAT[(size_t)c * kN + b * kC + l * 4], v);
    }
}
// transposing threshold: pert[i][c] = hard_sig(PAT[c][i] + diag bias); also bf16 copy.
__global__ __launch_bounds__(256) void thresholdT(float* __restrict__ pert,
                                                  const float* __restrict__ pb,
                                                  const int* __restrict__ gid) {
    __shared__ float s[32][33];
    const int tx = threadIdx.x, ty = threadIdx.y;   // 32 x 8
    const int c0 = blockIdx.x * 32;
    const int i0 = blockIdx.y * 32;
    const int b = i0 >> 8;
#pragma unroll
    for (int j = 0; j < 4; j++) {
        int cl = ty + j * 8;
        int c = c0 + cl;
        float v = 0.f;
        if (g_cnt[b * kN + c] > 0)
            v = g_PAT[(size_t)c * kN + i0 + tx];
        s[cl][tx] = v;
    }
    __syncthreads();
    const bool diag = (c0 >> 8) == b;
    const int gbase = diag ? (int)(gid[b] * (kC * kC)) : 0;
#pragma unroll
    for (int j = 0; j < 4; j++) {
        int il = ty + j * 8;
        int i = i0 + il;
        float v = s[tx][il];
        if (diag)
            v += pb[(size_t)gbase + (i & 255) * kC + ((c0 + tx) & 255)];
        float o = hard_sig(v);
        pert[(size_t)i * kN + c0 + tx] = o;
        g_pertBF[(size_t)i * kN + c0 + tx] = __float2bfloat16(o);
    }
}
__global__ void maskK(const float* __restrict__ x, const float* __restrict__ mW,
                      const int* __restrict__ gid,
                      float* __restrict__ Mo, float* __restrict__ xm) {
    size_t i4 = (size_t)blockIdx.x * blockDim.x + threadIdx.x;
    size_t e0 = i4 * 4;
    int n = (int)(e0 >> 8);
    int c = (int)(e0 & 255);
    int b = n >> 8;
    float4 w = *(const float4*)&mW[(size_t)gid[b] * kC * kC + (size_t)(n & 255) * kC + c];
    float4 xv = *(const float4*)&x[e0];
    float4 m, o;
    m.x = hard_sig(w.x); m.y = hard_sig(w.y); m.z = hard_sig(w.z); m.w = hard_sig(w.w);
    o.x = m.x * xv.x; o.y = m.y * xv.y; o.z = m.z * xv.z; o.w = m.w * xv.w;
    *(float4*)&Mo[e0] = m;
    *(float4*)&xm[e0] = o;
    __nv_bfloat162* d = (__nv_bfloat162*)g_xmBF;
    d[i4 * 2]     = __floats2bfloat162_rn(o.x, o.y);
    d[i4 * 2 + 1] = __floats2bfloat162_rn(o.z, o.w);
}
__global__ void cvtX(const float4* __restrict__ src, __nv_bfloat162* __restrict__ dst) {
    size_t i = (size_t)blockIdx.x * blockDim.x + threadIdx.x;
    float4 v = src[i];
    dst[2 * i]     = __floats2bfloat162_rn(v.x, v.y);
    dst[2 * i + 1] = __floats2bfloat162_rn(v.z, v.w);
}
// WT[n][k] = bf16(W[k][n]); W is [K x 128]
__global__ void cvtWT(const float* __restrict__ W, __nv_bfloat16* __restrict__ WT, int K) {
    int idx = blockIdx.x * 256 + threadIdx.x;
    int n = idx / K, k = idx - n * K;
    WT[idx] = __float2bfloat16(W[(size_t)k * kH + n]);
}

// ---------------- shared HMMA building blocks ----------------
#define ABUF (64 * 80)
#define BBUF (128 * 80)

#define HMMA_FRAG_DECL                                                                 \
    float acc[2][4][4];                                                                \
    _Pragma("unroll") for (int mt = 0; mt < 2; mt++)                                   \
    _Pragma("unroll") for (int nt = 0; nt < 4; nt++)                                   \
    _Pragma("unroll") for (int q = 0; q < 4; q++) acc[mt][nt][q] = 0.f;

#define HMMA_COMPUTE(saB, sbB)                                                         \
    _Pragma("unroll")                                                                  \
    for (int ks = 0; ks < 2; ks++) {                                                   \
        uint32_t af[2][4];                                                             \
        _Pragma("unroll")                                                              \
        for (int mt = 0; mt < 2; mt++) {                                               \
            uint32_t ad = (saB) + aLm0 + (uint32_t)(mt * 16 * 80 + ks * 32);           \
            asm volatile("ldmatrix.sync.aligned.m8n8.x4.shared.b16 {%0,%1,%2,%3}, [%4];" \
                         : "=r"(af[mt][0]), "=r"(af[mt][1]), "=r"(af[mt][2]),          \
                           "=r"(af[mt][3]) : "r"(ad));                                 \
        }                                                                              \
        _Pragma("unroll")                                                              \
        for (int nt = 0; nt < 4; nt++) {                                               \
            uint32_t b0, b1;                                                           \
            uint32_t bd = (sbB) + bLmRow + (uint32_t)(nt * 8 * 80 + ks * 32);          \
            asm volatile("ldmatrix.sync.aligned.m8n8.x2.shared.b16 {%0,%1}, [%2];"     \
                         : "=r"(b0), "=r"(b1) : "r"(bd));                              \
            _Pragma("unroll")                                                          \
            for (int mt = 0; mt < 2; mt++) {                                           \
                asm volatile(                                                          \
                    "mma.sync.aligned.m16n8k16.row.col.f32.bf16.bf16.f32 "             \
                    "{%0,%1,%2,%3}, {%4,%5,%6,%7}, {%8,%9}, {%0,%1,%2,%3};"            \
                    : "+f"(acc[mt][nt][0]), "+f"(acc[mt][nt][1]),                      \
                      "+f"(acc[mt][nt][2]), "+f"(acc[mt][nt][3])                       \
                    : "r"(af[mt][0]), "r"(af[mt][1]), "r"(af[mt][2]), "r"(af[mt][3]),  \
                      "r"(b0), "r"(b1));                                               \
            }                                                                          \
        }                                                                              \
    }

#define LOADCH_GEN(kt, bi) do {                                                        \
        int kk_ = (kt) * 32;                                                           \
        asm volatile("cp.async.cg.shared.global [%0], [%1], 16;"                       \
                     :: "r"(aDst + (bi) * ABUF), "l"(aSrc + kk_) : "memory");          \
        asm volatile("cp.async.cg.shared.global [%0], [%1], 16;"                       \
                     :: "r"(bDst0 + (bi) * BBUF), "l"(bSrc0 + kk_) : "memory");        \
        asm volatile("cp.async.cg.shared.global [%0], [%1], 16;"                       \
                     :: "r"(bDst1 + (bi) * BBUF), "l"(bSrc1 + kk_) : "memory");        \
        asm volatile("cp.async.commit_group;" ::: "memory");                           \
    } while (0)

// ---------------- big HMMA: Hb = pert[8192x8192]bf16 @ g_XWt^T ; 3-stage ----------------
#define NKCH (kN / 32)
__global__ __launch_bounds__(256) void hmmaGemm(const __nv_bfloat16* __restrict__ Abf,
                                                float* __restrict__ C) {
    __shared__ __align__(16) unsigned char smA[3 * ABUF];
    __shared__ __align__(16) unsigned char smB[3 * BBUF];
    const __nv_bfloat16* Bt = g_XWt;
    const int tid = threadIdx.x;
    const int lane = tid & 31, wid = tid >> 5;
    const int wm = wid >> 2, wn = wid & 3;
    const int row0 = blockIdx.x * 64;

    const uint32_t saBase = smem_u32(smA);
    const uint32_t sbBase = smem_u32(smB);

    const int ar = tid >> 2, aseg = tid & 3;
    const __nv_bfloat16* aSrc  = Abf + (size_t)(row0 + ar) * kN + aseg * 8;
    const __nv_bfloat16* bSrc0 = Bt + (size_t)ar * kN + aseg * 8;
    const __nv_bfloat16* bSrc1 = Bt + (size_t)(ar + 64) * kN + aseg * 8;
    const uint32_t aDst  = saBase + ar * 80 + aseg * 16;
    const uint32_t bDst0 = sbBase + ar * 80 + aseg * 16;
    const uint32_t bDst1 = sbBase + (ar + 64) * 80 + aseg * 16;

    HMMA_FRAG_DECL;

    const int l15 = lane & 15;
    const uint32_t aLm0 = (uint32_t)((wm * 32 + l15) * 80 + ((lane >> 4) & 1) * 16);
    const uint32_t bLmRow = (uint32_t)((wn * 32 + (l15 & 7)) * 80 + ((l15 >> 3) & 1) * 16);

    LOADCH_GEN(0, 0);
    LOADCH_GEN(1, 1);

    for (int kt = 0; kt < NKCH; kt++) {
        const int cur = kt % 3;
        if (kt + 2 < NKCH) {
            LOADCH_GEN(kt + 2, (kt + 2) % 3);
            asm volatile("cp.async.wait_group 2;" ::: "memory");
        } else if (kt + 1 < NKCH) {
            asm volatile("cp.async.wait_group 1;" ::: "memory");
        } else {
            asm volatile("cp.async.wait_group 0;" ::: "memory");
        }
        __syncthreads();
        HMMA_COMPUTE(saBase + cur * ABUF, sbBase + cur * BBUF);
        __syncthreads();
    }

    const int crow = row0 + wm * 32 + (lane >> 2);
    const int ccol = wn * 32 + (lane & 3) * 2;
#pragma unroll
    for (int mt = 0; mt < 2; mt++) {
#pragma unroll
        for (int nt = 0; nt < 4; nt++) {
            float2 v0 = make_float2(acc[mt][nt][0], acc[mt][nt][1]);
            float2 v1 = make_float2(acc[mt][nt][2], acc[mt][nt][3]);
            size_t o0 = (size_t)(crow + mt * 16) * kH + ccol + nt * 8;
            size_t o1 = (size_t)(crow + mt * 16 + 8) * kH + ccol + nt * 8;
            *(float2*)&C[o0] = v0;
            *(float2*)&C[o1] = v1;
            __nv_bfloat162 r0 = __floats2bfloat162_rn(fmaxf(v0.x, 0.f), fmaxf(v0.y, 0.f));
            __nv_bfloat162 r1 = __floats2bfloat162_rn(fmaxf(v1.x, 0.f), fmaxf(v1.y, 0.f));
            *(__nv_bfloat162*)&g_HbBF[o0] = r0;
            *(__nv_bfloat162*)&g_HbBF[o1] = r1;
        }
    }
}

// ---------------- narrow HMMA: XWt (K-major) + XWrm (row-major) = A @ WT^T bf16 ----------------
template <int K>
__global__ __launch_bounds__(256) void hmmaNarrow(const __nv_bfloat16* __restrict__ Abf,
                                                  const __nv_bfloat16* __restrict__ Bt) {
    __shared__ __align__(16) unsigned char smA[2 * ABUF];
    __shared__ __align__(16) unsigned char smB[2 * BBUF];
    __shared__ __align__(16) __nv_bfloat16 Ts[kH * 72];
    const int tid = threadIdx.x;
    const int lane = tid & 31, wid = tid >> 5;
    const int wm = wid >> 2, wn = wid & 3;
    const int row0 = blockIdx.x * 64;
    const int nch = K / 32;

    const uint32_t saBase = smem_u32(smA);
    const uint32_t sbBase = smem_u32(smB);

    const int ar = tid >> 2, aseg = tid & 3;
    const __nv_bfloat16* aSrc  = Abf + (size_t)(row0 + ar) * K + aseg * 8;
    const __nv_bfloat16* bSrc0 = Bt + (size_t)ar * K + aseg * 8;
    const __nv_bfloat16* bSrc1 = Bt + (size_t)(ar + 64) * K + aseg * 8;
    const uint32_t aDst  = saBase + ar * 80 + aseg * 16;
    const uint32_t bDst0 = sbBase + ar * 80 + aseg * 16;
    const uint32_t bDst1 = sbBase + (ar + 64) * 80 + aseg * 16;

    HMMA_FRAG_DECL;

    const int l15 = lane & 15;
    const uint32_t aLm0 = (uint32_t)((wm * 32 + l15) * 80 + ((lane >> 4) & 1) * 16);
    const uint32_t bLmRow = (uint32_t)((wn * 32 + (l15 & 7)) * 80 + ((l15 >> 3) & 1) * 16);

    LOADCH_GEN(0, 0);
    for (int kt = 0; kt < nch; kt++) {
        const int cur = kt & 1;
        if (kt + 1 < nch) {
            LOADCH_GEN(kt + 1, cur ^ 1);
            asm volatile("cp.async.wait_group 1;" ::: "memory");
        } else {
            asm volatile("cp.async.wait_group 0;" ::: "memory");
        }
        __syncthreads();
        HMMA_COMPUTE(saBase + cur * ABUF, sbBase + cur * BBUF);
        __syncthreads();
    }

    const int rloc = wm * 32 + (lane >> 2);
    const int ccol = wn * 32 + (lane & 3) * 2;
    // row-major bf16 out + staging for K-major
#pragma unroll
    for (int mt = 0; mt < 2; mt++) {
#pragma unroll
        for (int nt = 0; nt < 4; nt++) {
            int c = ccol + nt * 8;
            __nv_bfloat162 p0 = __floats2bfloat162_rn(acc[mt][nt][0], acc[mt][nt][1]);
            __nv_bfloat162 p1 = __floats2bfloat162_rn(acc[mt][nt][2], acc[mt][nt][3]);
            *(__nv_bfloat162*)&g_XWrm[(size_t)(row0 + rloc + mt * 16) * kH + c] = p0;
            *(__nv_bfloat162*)&g_XWrm[(size_t)(row0 + rloc + mt * 16 + 8) * kH + c] = p1;
            Ts[(c + 0) * 72 + rloc + mt * 16]     = __float2bfloat16(acc[mt][nt][0]);
            Ts[(c + 1) * 72 + rloc + mt * 16]     = __float2bfloat16(acc[mt][nt][1]);
            Ts[(c + 0) * 72 + rloc + mt * 16 + 8] = __float2bfloat16(acc[mt][nt][2]);
            Ts[(c + 1) * 72 + rloc + mt * 16 + 8] = __float2bfloat16(acc[mt][nt][3]);
        }
    }
    __syncthreads();
    {
        int col = tid >> 1, half = tid & 1;
        const uint4* src = (const uint4*)&Ts[col * 72 + half * 32];
        uint4* dst = (uint4*)&g_XWt[(size_t)col * kN + row0 + half * 32];
#pragma unroll
        for (int q = 0; q < 4; q++) dst[q] = src[q];
    }
}

// ---------------- pooling + MLP + sigmoid (1024 threads: 8 row-chunks x 128 feat) ----------------
__global__ __launch_bounds__(1024) void poolMlp(const float* __restrict__ mlpW,
                                                const float* __restrict__ mlpb,
                                                float* __restrict__ outp) {
    int g = blockIdx.x;
    int tid = threadIdx.x;
    int ch = tid >> 7, f = tid & 127;
    const float* base = g_Hb + (size_t)g * kC * kH;
    float s = 0.f, m = 0.f;
    for (int r = ch * 32; r < ch * 32 + 32; r++) {
        float v = base[(size_t)r * kH + f];
        v = v > 0.f ? v : 0.f;
        s += v;
        m = v > m ? v : m;
    }
    __shared__ float ss[8][128], sm[8][128];
    __shared__ float r0[128], r1[128];
    ss[ch][f] = s; sm[ch][f] = m;
    __syncthreads();
    if (tid < 128) {
        float S = 0.f, M = 0.f;
#pragma unroll
        for (int c2 = 0; c2 < 8; c2++) {
            S += ss[c2][f];
            M = sm[c2][f] > M ? sm[c2][f] : M;
        }
        S *= (1.0f / kC);
        r0[f] = S * mlpW[f * 2 + 0] + M * mlpW[(kH + f) * 2 + 0];
        r1[f] = S * mlpW[f * 2 + 1] + M * mlpW[(kH + f) * 2 + 1];
    }
    __syncthreads();
    for (int st = 64; st > 0; st >>= 1) {
        if (tid < st) { r0[tid] += r0[tid + st]; r1[tid] += r1[tid + st]; }
        __syncthreads();
    }
    if (tid == 0) {
        outp[g * 2 + 0] = 1.f / (1.f + expf(-(r0[0] + mlpb[0])));
        outp[g * 2 + 1] = 1.f / (1.f + expf(-(r1[0] + mlpb[1])));
    }
}

// ---------------- driver ----------------
extern "C" void kernel_launch(void* const* d_in, const int* in_sizes, int n_in,
                              void* d_out, int out_size) {
    const float* x    = (const float*)d_in[0];
    const int*   ei   = (const int*)d_in[1];
    const int*   gid  = (const int*)d_in[2];
    const float* pW   = (const float*)d_in[4];
    const float* pb   = (const float*)d_in[5];
    const float* mW   = (const float*)d_in[6];
    const float* w0   = (const float*)d_in[7];
    const float* w1   = (const float*)d_in[8];
    const float* w2   = (const float*)d_in[9];
    const float* mlpW = (const float*)d_in[10];
    const float* mlpb = (const float*)d_in[11];

    float* out  = (float*)d_out;
    float* adj  = out;
    float* pert = out + kNN;
    float* Mo   = out + 2 * kNN;
    float* pred = Mo + (size_t)kN * kC;
    float* aug  = pred + kB * 2;
    float* xm   = aug + kB * 2;

    __nv_bfloat16 *pertBF, *xBF, *xmBF, *HbBF, *wT;
    int *cnt, *rowCnt;
    cudaGetSymbolAddress((void**)&pertBF, g_pertBF);
    cudaGetSymbolAddress((void**)&xBF, g_xBF);
    cudaGetSymbolAddress((void**)&xmBF, g_xmBF);
    cudaGetSymbolAddress((void**)&HbBF, g_HbBF);
    cudaGetSymbolAddress((void**)&wT, g_wT);
    cudaGetSymbolAddress((void**)&cnt, g_cnt);
    cudaGetSymbolAddress((void**)&rowCnt, g_rowCnt);
    __nv_bfloat16* wT0 = wT;
    __nv_bfloat16* wT1 = wT + kC * kH;
    __nv_bfloat16* wT2 = wT + 2 * kC * kH;

    const int Z64M = (int)(kNN / 4 / 256);
    const int ZC   = (int)((size_t)kB * kN * 4 / 16 / 256);

    zeroBuf<<<Z64M, 256>>>((float4*)adj);
    zeroBuf<<<ZC, 256>>>((float4*)cnt);
    zeroBuf<<<kN * 4 / 16 / 256, 256>>>((float4*)rowCnt);
    transposeP<<<dim3(8, 8, kB), dim3(32, 8)>>>(pW, gid);
    scatterEdges<<<kE / 256, 256>>>(ei, adj);
    scanRows<<<1, 1024>>>();
    fillCSR<<<kE / 256, 256>>>(ei);
    scatterPstore<<<kE / 4, 256>>>(ei);
    scatterPred<<<kE / 4, 256>>>(ei);
    thresholdT<<<dim3(kN / 32, kN / 32), dim3(32, 8)>>>(pert, pb, gid);
    maskK<<<(int)((size_t)kN * kC / 4 / 256), 256>>>(x, mW, gid, Mo, xm);
    cvtX<<<(int)((size_t)kN * kC / 4 / 256), 256>>>((const float4*)x, (__nv_bfloat162*)xBF);
    cvtWT<<<kC * kH / 256, 256>>>(w0, wT0, kC);
    cvtWT<<<kH * kH / 256, 256>>>(w1, wT1, kH);
    cvtWT<<<kH * kH / 256, 256>>>(w2, wT2, kH);

    // ---- predictor on (x, adj): CSR SpMM path ----
    hmmaNarrow<kC><<<kN / 64, 256>>>(xBF, wT0);
    spmmCSR<<<kN, 128>>>();
    hmmaNarrow<kH><<<kN / 64, 256>>>(HbBF, wT1);
    spmmCSR<<<kN, 128>>>();
    hmmaNarrow<kH><<<kN / 64, 256>>>(HbBF, wT2);
    spmmCSR<<<kN, 128>>>();
    poolMlp<<<kB, 1024>>>(mlpW, mlpb, pred);

    // ---- predictor on (x_masked, pert_adj): dense HMMA path ----
    hmmaNarrow<kC><<<kN / 64, 256>>>(xmBF, wT0);
    hmmaGemm<<<kN / 64, 256>>>(pertBF, g_Hb);
    hmmaNarrow<kH><<<kN / 64, 256>>>(HbBF, wT1);
    hmmaGemm<<<kN / 64, 256>>>(pertBF, g_Hb);
    hmmaNarrow<kH><<<kN / 64, 256>>>(HbBF, wT2);
    hmmaGemm<<<kN / 64, 256>>>(pertBF, g_Hb);
    poolMlp<<<kB, 1024>>>(mlpW, mlpb, aug);
}